// round 1
// baseline (speedup 1.0000x reference)
#include <cuda_runtime.h>
#include <math.h>

#define NN 100000
#define NE 1600000
#define FIN 512
#define D1 64
#define D2 256

// ---- scratch (device globals; no allocation allowed) ----
__device__ float g_dinv[NN];
__device__ float g_xw1[(size_t)NN * D1];   // x @ W1
__device__ float g_h1 [(size_t)NN * D1];   // relu(A xw1 + b1)
__device__ float g_ah1[(size_t)NN * D1];   // A h1
__device__ float g_h2 [(size_t)NN * D2];   // relu(ah1 @ W2 + b2)
__device__ float g_z0 [NN];                // h2 @ W3
__device__ float g_z  [NN];                // A z0 + b3

// ---------------- degree / dinv ----------------
__global__ void k_deg_init() {
    int i = blockIdx.x * blockDim.x + threadIdx.x;
    if (i < NN) g_dinv[i] = 1.0f;   // self loop
}
__global__ void k_deg_count(const int* __restrict__ dst) {
    int e = blockIdx.x * blockDim.x + threadIdx.x;
    if (e < NE) atomicAdd(&g_dinv[dst[e]], 1.0f);
}
__global__ void k_deg_fin() {
    int i = blockIdx.x * blockDim.x + threadIdx.x;
    if (i < NN) g_dinv[i] = rsqrtf(g_dinv[i]);
}

// ---------------- GEMM1: C[M,64] = A[M,512] @ B[512,64] ----------------
__global__ __launch_bounds__(128) void k_gemm1(const float* __restrict__ A,
                                               const float* __restrict__ B,
                                               float* __restrict__ C) {
    __shared__ float As[32][132];
    __shared__ float Bs[32][68];
    int tid = threadIdx.x;
    int bm  = blockIdx.x * 128;
    int ti  = tid & 15;   // 0..15 -> 8 rows each
    int tj  = tid >> 4;   // 0..7  -> 8 cols each
    float acc[8][8];
#pragma unroll
    for (int i = 0; i < 8; i++)
#pragma unroll
        for (int j = 0; j < 8; j++) acc[i][j] = 0.f;

    int gr = bm + tid;
    bool valid = gr < NN;

    for (int k0 = 0; k0 < FIN; k0 += 32) {
        // A tile: row 'tid', 32 k's, stored transposed As[k][m]
#pragma unroll
        for (int kk = 0; kk < 8; kk++) {
            float4 v = valid ? *(const float4*)(A + (size_t)gr * FIN + k0 + kk * 4)
                             : make_float4(0.f, 0.f, 0.f, 0.f);
            As[kk * 4 + 0][tid] = v.x;
            As[kk * 4 + 1][tid] = v.y;
            As[kk * 4 + 2][tid] = v.z;
            As[kk * 4 + 3][tid] = v.w;
        }
        // B tile 32x64
#pragma unroll
        for (int it = 0; it < 4; it++) {
            int kr = it * 8 + (tid >> 4);
            int nc = (tid & 15) * 4;
            float4 v = *(const float4*)(B + (size_t)(k0 + kr) * 64 + nc);
            *(float4*)&Bs[kr][nc] = v;
        }
        __syncthreads();
#pragma unroll
        for (int k = 0; k < 32; k++) {
            float4 a0 = *(const float4*)&As[k][ti * 8];
            float4 a1 = *(const float4*)&As[k][ti * 8 + 4];
            float4 b0 = *(const float4*)&Bs[k][tj * 8];
            float4 b1 = *(const float4*)&Bs[k][tj * 8 + 4];
            float a[8] = {a0.x, a0.y, a0.z, a0.w, a1.x, a1.y, a1.z, a1.w};
            float b[8] = {b0.x, b0.y, b0.z, b0.w, b1.x, b1.y, b1.z, b1.w};
#pragma unroll
            for (int i = 0; i < 8; i++)
#pragma unroll
                for (int j = 0; j < 8; j++) acc[i][j] += a[i] * b[j];
        }
        __syncthreads();
    }
#pragma unroll
    for (int i = 0; i < 8; i++) {
        int r = bm + ti * 8 + i;
        if (r < NN) {
            *(float4*)(C + (size_t)r * 64 + tj * 8)     = make_float4(acc[i][0], acc[i][1], acc[i][2], acc[i][3]);
            *(float4*)(C + (size_t)r * 64 + tj * 8 + 4) = make_float4(acc[i][4], acc[i][5], acc[i][6], acc[i][7]);
    }
    }
}

// ---------------- GEMM2: C[M,256] = relu(A[M,64] @ B[64,256] + bias) ----------------
__global__ __launch_bounds__(128) void k_gemm2(const float* __restrict__ A,
                                               const float* __restrict__ B,
                                               const float* __restrict__ bias,
                                               float* __restrict__ C) {
    __shared__ float As[32][132];
    __shared__ float Bs[32][68];
    int tid = threadIdx.x;
    int bm  = blockIdx.x * 128;
    int bn  = blockIdx.y * 64;
    int ti  = tid & 15;
    int tj  = tid >> 4;
    float acc[8][8];
#pragma unroll
    for (int i = 0; i < 8; i++)
#pragma unroll
        for (int j = 0; j < 8; j++) acc[i][j] = 0.f;

    int gr = bm + tid;
    bool valid = gr < NN;

    for (int k0 = 0; k0 < D1; k0 += 32) {
#pragma unroll
        for (int kk = 0; kk < 8; kk++) {
            float4 v = valid ? *(const float4*)(A + (size_t)gr * D1 + k0 + kk * 4)
                             : make_float4(0.f, 0.f, 0.f, 0.f);
            As[kk * 4 + 0][tid] = v.x;
            As[kk * 4 + 1][tid] = v.y;
            As[kk * 4 + 2][tid] = v.z;
            As[kk * 4 + 3][tid] = v.w;
        }
#pragma unroll
        for (int it = 0; it < 4; it++) {
            int kr = it * 8 + (tid >> 4);
            int nc = (tid & 15) * 4;
            float4 v = *(const float4*)(B + (size_t)(k0 + kr) * D2 + bn + nc);
            *(float4*)&Bs[kr][nc] = v;
        }
        __syncthreads();
#pragma unroll
        for (int k = 0; k < 32; k++) {
            float4 a0 = *(const float4*)&As[k][ti * 8];
            float4 a1 = *(const float4*)&As[k][ti * 8 + 4];
            float4 b0 = *(const float4*)&Bs[k][tj * 8];
            float4 b1 = *(const float4*)&Bs[k][tj * 8 + 4];
            float a[8] = {a0.x, a0.y, a0.z, a0.w, a1.x, a1.y, a1.z, a1.w};
            float b[8] = {b0.x, b0.y, b0.z, b0.w, b1.x, b1.y, b1.z, b1.w};
#pragma unroll
            for (int i = 0; i < 8; i++)
#pragma unroll
                for (int j = 0; j < 8; j++) acc[i][j] += a[i] * b[j];
        }
        __syncthreads();
    }
    float4 bb0 = *(const float4*)&bias[bn + tj * 8];
    float4 bb1 = *(const float4*)&bias[bn + tj * 8 + 4];
    float bv[8] = {bb0.x, bb0.y, bb0.z, bb0.w, bb1.x, bb1.y, bb1.z, bb1.w};
#pragma unroll
    for (int i = 0; i < 8; i++) {
        int r = bm + ti * 8 + i;
        if (r < NN) {
            float o[8];
#pragma unroll
            for (int j = 0; j < 8; j++) o[j] = fmaxf(acc[i][j] + bv[j], 0.f);
            *(float4*)(C + (size_t)r * D2 + bn + tj * 8)     = make_float4(o[0], o[1], o[2], o[3]);
            *(float4*)(C + (size_t)r * D2 + bn + tj * 8 + 4) = make_float4(o[4], o[5], o[6], o[7]);
        }
    }
}

// ---------------- 64-dim aggregation ----------------
// self-loop init: out[i,:] = in[i,:] * dinv[i]^2
__global__ void k_selfinit64(const float* __restrict__ in, float* __restrict__ out) {
    int t = blockIdx.x * blockDim.x + threadIdx.x;   // over NN*16 float4s
    if (t >= NN * 16) return;
    int node = t >> 4;
    float di = g_dinv[node];
    float s  = di * di;
    float4 v = ((const float4*)in)[t];
    v.x *= s; v.y *= s; v.z *= s; v.w *= s;
    ((float4*)out)[t] = v;
}

// edge scatter: one warp per edge, 2 floats per lane
__global__ __launch_bounds__(256) void k_aggedge64(const float* __restrict__ in,
                                                   float* __restrict__ out,
                                                   const int* __restrict__ src,
                                                   const int* __restrict__ dst) {
    int w = (blockIdx.x * blockDim.x + threadIdx.x) >> 5;
    if (w >= NE) return;
    int lane = threadIdx.x & 31;
    int s = __ldg(&src[w]);
    int d = __ldg(&dst[w]);
    float wt = g_dinv[s] * g_dinv[d];
    float2 v = ((const float2*)(in + (size_t)s * 64))[lane];
    float* o = out + (size_t)d * 64 + lane * 2;
    atomicAdd(o,     v.x * wt);
    atomicAdd(o + 1, v.y * wt);
}

__global__ void k_bias_relu64(float* __restrict__ h, const float* __restrict__ b) {
    int t = blockIdx.x * blockDim.x + threadIdx.x;   // NN*16 float4s
    if (t >= NN * 16) return;
    float4 bb = ((const float4*)b)[t & 15];
    float4 v  = ((float4*)h)[t];
    v.x = fmaxf(v.x + bb.x, 0.f);
    v.y = fmaxf(v.y + bb.y, 0.f);
    v.z = fmaxf(v.z + bb.z, 0.f);
    v.w = fmaxf(v.w + bb.w, 0.f);
    ((float4*)h)[t] = v;
}

// ---------------- layer 3 ----------------
__global__ __launch_bounds__(256) void k_matvec(const float* __restrict__ H,
                                                const float* __restrict__ W3) {
    int warp = (blockIdx.x * blockDim.x + threadIdx.x) >> 5;
    int lane = threadIdx.x & 31;
    if (warp >= NN) return;
    const float4* row = (const float4*)(H + (size_t)warp * D2);
    const float4* w   = (const float4*)W3;
    float4 a0 = row[lane], a1 = row[lane + 32];
    float4 w0 = w[lane],   w1 = w[lane + 32];
    float s = a0.x * w0.x + a0.y * w0.y + a0.z * w0.z + a0.w * w0.w
            + a1.x * w1.x + a1.y * w1.y + a1.z * w1.z + a1.w * w1.w;
#pragma unroll
    for (int off = 16; off; off >>= 1) s += __shfl_down_sync(0xffffffffu, s, off);
    if (lane == 0) g_z0[warp] = s;
}

__global__ void k_zinit(const float* __restrict__ b3) {
    int i = blockIdx.x * blockDim.x + threadIdx.x;
    if (i < NN) {
        float di = g_dinv[i];
        g_z[i] = g_z0[i] * di * di + b3[0];
    }
}
__global__ void k_zedge(const int* __restrict__ src, const int* __restrict__ dst) {
    int e = blockIdx.x * blockDim.x + threadIdx.x;
    if (e < NE) {
        int s = src[e], d = dst[e];
        atomicAdd(&g_z[d], g_z0[s] * g_dinv[s] * g_dinv[d]);
    }
}

// ---------------- loss ----------------
__global__ void k_zero(float* out) {
    if (blockIdx.x == 0 && threadIdx.x == 0) out[0] = 0.f;
}
__global__ void k_loss(const float* __restrict__ y, float* __restrict__ out) {
    __shared__ float red[256];
    int i = blockIdx.x * blockDim.x + threadIdx.x;
    float v = 0.f;
    if (i < NN) {
        float z = g_z[i];
        float t = y[i];
        // BCE-with-logits, stable: max(z,0) - z*y + log1p(exp(-|z|))
        v = fmaxf(z, 0.f) - z * t + log1pf(expf(-fabsf(z)));
    }
    red[threadIdx.x] = v;
    __syncthreads();
    for (int s = 128; s > 0; s >>= 1) {
        if (threadIdx.x < s) red[threadIdx.x] += red[threadIdx.x + s];
        __syncthreads();
    }
    if (threadIdx.x == 0) atomicAdd(out, red[0] * (1.0f / NN));
}

// ---------------- launcher ----------------
extern "C" void kernel_launch(void* const* d_in, const int* in_sizes, int n_in,
                              void* d_out, int out_size) {
    const float* x  = (const float*)d_in[0];
    const int*   ei = (const int*)  d_in[1];
    const float* y  = (const float*)d_in[2];
    const float* W1 = (const float*)d_in[3];
    const float* b1 = (const float*)d_in[4];
    const float* W2 = (const float*)d_in[5];
    const float* b2 = (const float*)d_in[6];
    const float* W3 = (const float*)d_in[7];
    const float* b3 = (const float*)d_in[8];
    const int* src = ei;
    const int* dst = ei + NE;
    float* out = (float*)d_out;

    float *p_xw1, *p_h1, *p_ah1, *p_h2;
    cudaGetSymbolAddress((void**)&p_xw1, g_xw1);
    cudaGetSymbolAddress((void**)&p_h1,  g_h1);
    cudaGetSymbolAddress((void**)&p_ah1, g_ah1);
    cudaGetSymbolAddress((void**)&p_h2,  g_h2);

    const int T = 256;
    // degrees
    k_deg_init<<<(NN + T - 1) / T, T>>>();
    k_deg_count<<<(NE + T - 1) / T, T>>>(dst);
    k_deg_fin<<<(NN + T - 1) / T, T>>>();

    // layer 1: xw1 = x@W1 ; h1 = relu(A xw1 + b1)
    k_gemm1<<<(NN + 127) / 128, 128>>>(x, W1, p_xw1);
    k_selfinit64<<<(NN * 16 + T - 1) / T, T>>>(p_xw1, p_h1);
    k_aggedge64<<<(NE * 32 + T - 1) / T, T>>>(p_xw1, p_h1, src, dst);
    k_bias_relu64<<<(NN * 16 + T - 1) / T, T>>>(p_h1, b1);

    // layer 2: ah1 = A h1 ; h2 = relu(ah1@W2 + b2)
    k_selfinit64<<<(NN * 16 + T - 1) / T, T>>>(p_h1, p_ah1);
    k_aggedge64<<<(NE * 32 + T - 1) / T, T>>>(p_h1, p_ah1, src, dst);
    dim3 g2((NN + 127) / 128, D2 / 64);
    k_gemm2<<<g2, 128>>>(p_ah1, W2, b2, p_h2);

    // layer 3: z0 = h2@W3 ; z = A z0 + b3
    k_matvec<<<(NN * 32 + T - 1) / T, T>>>(p_h2, W3);
    k_zinit<<<(NN + T - 1) / T, T>>>(b3);
    k_zedge<<<(NE + T - 1) / T, T>>>(src, dst);

    // loss
    k_zero<<<1, 32>>>(out);
    k_loss<<<(NN + T - 1) / T, T>>>(y, out);
}

// round 2
// speedup vs baseline: 1.3591x; 1.3591x over previous
#include <cuda_runtime.h>
#include <math.h>

#define NN 100000
#define NE 1600000
#define FIN 512
#define D1 64
#define D2 256
#define SCAN_B 1024
#define SCAN_NB ((NN + SCAN_B - 1) / SCAN_B)

typedef unsigned long long ull;

// ---- scratch (device globals; no allocation allowed) ----
__device__ float g_dinv[NN];
__device__ int   g_cnt[NN];          // histogram, then reused as fill-offsets
__device__ int   g_tmp[NN];          // inclusive scan of cnt
__device__ int   g_bsum[SCAN_NB];
__device__ int   g_rowstart[NN + 1];
__device__ int   g_csrsrc[NE];
__device__ float g_xw1[(size_t)NN * D1];   // x @ W1
__device__ float g_h1 [(size_t)NN * D1];   // relu(A xw1 + b1)
__device__ float g_ah1[(size_t)NN * D1];   // A h1
__device__ float g_h2 [(size_t)NN * D2];   // relu(ah1 @ W2 + b2)
__device__ float g_z0 [NN];                // h2 @ W3
__device__ float g_z  [NN];                // A z0 + b3

// ---------------- f32x2 helpers ----------------
__device__ __forceinline__ void ffma2(ull& d, ull a, ull b) {
    asm("fma.rn.f32x2 %0, %1, %2, %0;" : "+l"(d) : "l"(a), "l"(b));
}
__device__ __forceinline__ void unpk2(ull v, float& lo, float& hi) {
    asm("mov.b64 {%0, %1}, %2;" : "=f"(lo), "=f"(hi) : "l"(v));
}

// ---------------- CSR build ----------------
__global__ void k_clear() {
    int i = blockIdx.x * blockDim.x + threadIdx.x;
    if (i < NN) g_cnt[i] = 0;
}
__global__ void k_hist(const int* __restrict__ dst) {
    int e = blockIdx.x * blockDim.x + threadIdx.x;
    if (e < NE) atomicAdd(&g_cnt[dst[e]], 1);
}
__global__ __launch_bounds__(SCAN_B) void k_scan1() {
    __shared__ int sh[SCAN_B];
    int t = threadIdx.x;
    int i = blockIdx.x * SCAN_B + t;
    sh[t] = (i < NN) ? g_cnt[i] : 0;
    __syncthreads();
#pragma unroll
    for (int off = 1; off < SCAN_B; off <<= 1) {
        int v = (t >= off) ? sh[t - off] : 0;
        __syncthreads();
        sh[t] += v;
        __syncthreads();
    }
    if (i < NN) g_tmp[i] = sh[t];
    if (t == SCAN_B - 1) g_bsum[blockIdx.x] = sh[t];
}
__global__ void k_scan2() {
    if (threadIdx.x == 0) {
        int run = 0;
        for (int b = 0; b < SCAN_NB; b++) { int v = g_bsum[b]; g_bsum[b] = run; run += v; }
    }
}
__global__ void k_scan3() {
    int i = blockIdx.x * blockDim.x + threadIdx.x;
    if (i < NN) {
        g_rowstart[i + 1] = g_tmp[i] + g_bsum[i >> 10];
        if (i == 0) g_rowstart[0] = 0;
        int c = g_cnt[i];
        g_dinv[i] = rsqrtf((float)c + 1.0f);   // +1 self loop
        g_cnt[i] = 0;                          // reuse as fill offset
    }
}
__global__ void k_fill(const int* __restrict__ src, const int* __restrict__ dst) {
    int e = blockIdx.x * blockDim.x + threadIdx.x;
    if (e < NE) {
        int d = dst[e];
        int pos = g_rowstart[d] + atomicAdd(&g_cnt[d], 1);
        g_csrsrc[pos] = src[e];
    }
}

// ---------------- GEMM1: C[M,64] = A[M,512] @ B[512,64]  (f32x2) ----------------
__global__ __launch_bounds__(128) void k_gemm1(const float* __restrict__ A,
                                               const float* __restrict__ B,
                                               float* __restrict__ C) {
    __shared__ float As[32][132];    // transposed: As[k][m]
    __shared__ float Bs2[32][132];   // duplicated: Bs2[k][2j]=Bs2[k][2j+1]=B[k][j]
    int tid = threadIdx.x;
    int bm  = blockIdx.x * 128;
    int ti  = tid & 15;   // 8 rows each (4 pairs)
    int tj  = tid >> 4;   // 8 cols each
    ull accp[4][8];
#pragma unroll
    for (int p = 0; p < 4; p++)
#pragma unroll
        for (int j = 0; j < 8; j++) accp[p][j] = 0ull;

    int gr = bm + tid;
    bool valid = gr < NN;

    for (int k0 = 0; k0 < FIN; k0 += 32) {
#pragma unroll
        for (int kk = 0; kk < 8; kk++) {
            float4 v = valid ? *(const float4*)(A + (size_t)gr * FIN + k0 + kk * 4)
                             : make_float4(0.f, 0.f, 0.f, 0.f);
            As[kk * 4 + 0][tid] = v.x;
            As[kk * 4 + 1][tid] = v.y;
            As[kk * 4 + 2][tid] = v.z;
            As[kk * 4 + 3][tid] = v.w;
        }
#pragma unroll
        for (int it = 0; it < 4; it++) {
            int kr = it * 8 + (tid >> 4);
            int nc = (tid & 15) * 4;
            float4 v = *(const float4*)(B + (size_t)(k0 + kr) * 64 + nc);
            float2* brow = (float2*)&Bs2[kr][nc * 2];
            brow[0] = make_float2(v.x, v.x);
            brow[1] = make_float2(v.y, v.y);
            brow[2] = make_float2(v.z, v.z);
            brow[3] = make_float2(v.w, v.w);
        }
        __syncthreads();
#pragma unroll
        for (int k = 0; k < 32; k++) {
            const ulonglong2* ap = (const ulonglong2*)&As[k][ti * 8];
            ulonglong2 a01 = ap[0], a23 = ap[1];
            ull pa[4] = {a01.x, a01.y, a23.x, a23.y};
            const ulonglong2* bp = (const ulonglong2*)&Bs2[k][tj * 16];
            ulonglong2 b0 = bp[0], b1 = bp[1], b2 = bp[2], b3 = bp[3];
            ull pb[8] = {b0.x, b0.y, b1.x, b1.y, b2.x, b2.y, b3.x, b3.y};
#pragma unroll
            for (int p = 0; p < 4; p++)
#pragma unroll
                for (int j = 0; j < 8; j++) ffma2(accp[p][j], pa[p], pb[j]);
        }
        __syncthreads();
    }
#pragma unroll
    for (int p = 0; p < 4; p++) {
        float lo[8], hi[8];
#pragma unroll
        for (int j = 0; j < 8; j++) unpk2(accp[p][j], lo[j], hi[j]);
        int r0 = bm + ti * 8 + 2 * p;
        if (r0 < NN) {
            *(float4*)(C + (size_t)r0 * 64 + tj * 8)     = make_float4(lo[0], lo[1], lo[2], lo[3]);
            *(float4*)(C + (size_t)r0 * 64 + tj * 8 + 4) = make_float4(lo[4], lo[5], lo[6], lo[7]);
        }
        if (r0 + 1 < NN) {
            *(float4*)(C + (size_t)(r0 + 1) * 64 + tj * 8)     = make_float4(hi[0], hi[1], hi[2], hi[3]);
            *(float4*)(C + (size_t)(r0 + 1) * 64 + tj * 8 + 4) = make_float4(hi[4], hi[5], hi[6], hi[7]);
        }
    }
}

// ---------------- GEMM2: C[M,256] = relu(A[M,64] @ B[64,256] + bias)  (f32x2) ----------------
__global__ __launch_bounds__(128) void k_gemm2(const float* __restrict__ A,
                                               const float* __restrict__ B,
                                               const float* __restrict__ bias,
                                               float* __restrict__ C) {
    __shared__ float As[32][132];
    __shared__ float Bs2[32][132];
    int tid = threadIdx.x;
    int bm  = blockIdx.x * 128;
    int bn  = blockIdx.y * 64;
    int ti  = tid & 15;
    int tj  = tid >> 4;
    ull accp[4][8];
#pragma unroll
    for (int p = 0; p < 4; p++)
#pragma unroll
        for (int j = 0; j < 8; j++) accp[p][j] = 0ull;

    int gr = bm + tid;
    bool valid = gr < NN;

    for (int k0 = 0; k0 < D1; k0 += 32) {
#pragma unroll
        for (int kk = 0; kk < 8; kk++) {
            float4 v = valid ? *(const float4*)(A + (size_t)gr * D1 + k0 + kk * 4)
                             : make_float4(0.f, 0.f, 0.f, 0.f);
            As[kk * 4 + 0][tid] = v.x;
            As[kk * 4 + 1][tid] = v.y;
            As[kk * 4 + 2][tid] = v.z;
            As[kk * 4 + 3][tid] = v.w;
        }
#pragma unroll
        for (int it = 0; it < 4; it++) {
            int kr = it * 8 + (tid >> 4);
            int nc = (tid & 15) * 4;
            float4 v = *(const float4*)(B + (size_t)(k0 + kr) * D2 + bn + nc);
            float2* brow = (float2*)&Bs2[kr][nc * 2];
            brow[0] = make_float2(v.x, v.x);
            brow[1] = make_float2(v.y, v.y);
            brow[2] = make_float2(v.z, v.z);
            brow[3] = make_float2(v.w, v.w);
        }
        __syncthreads();
#pragma unroll
        for (int k = 0; k < 32; k++) {
            const ulonglong2* ap = (const ulonglong2*)&As[k][ti * 8];
            ulonglong2 a01 = ap[0], a23 = ap[1];
            ull pa[4] = {a01.x, a01.y, a23.x, a23.y};
            const ulonglong2* bp = (const ulonglong2*)&Bs2[k][tj * 16];
            ulonglong2 b0 = bp[0], b1 = bp[1], b2 = bp[2], b3 = bp[3];
            ull pb[8] = {b0.x, b0.y, b1.x, b1.y, b2.x, b2.y, b3.x, b3.y};
#pragma unroll
            for (int p = 0; p < 4; p++)
#pragma unroll
                for (int j = 0; j < 8; j++) ffma2(accp[p][j], pa[p], pb[j]);
        }
        __syncthreads();
    }
    float4 bb0 = *(const float4*)&bias[bn + tj * 8];
    float4 bb1 = *(const float4*)&bias[bn + tj * 8 + 4];
    float bv[8] = {bb0.x, bb0.y, bb0.z, bb0.w, bb1.x, bb1.y, bb1.z, bb1.w};
#pragma unroll
    for (int p = 0; p < 4; p++) {
        float lo[8], hi[8];
#pragma unroll
        for (int j = 0; j < 8; j++) { unpk2(accp[p][j], lo[j], hi[j]);
            lo[j] = fmaxf(lo[j] + bv[j], 0.f); hi[j] = fmaxf(hi[j] + bv[j], 0.f); }
        int r0 = bm + ti * 8 + 2 * p;
        if (r0 < NN) {
            *(float4*)(C + (size_t)r0 * D2 + bn + tj * 8)     = make_float4(lo[0], lo[1], lo[2], lo[3]);
            *(float4*)(C + (size_t)r0 * D2 + bn + tj * 8 + 4) = make_float4(lo[4], lo[5], lo[6], lo[7]);
        }
        if (r0 + 1 < NN) {
            *(float4*)(C + (size_t)(r0 + 1) * D2 + bn + tj * 8)     = make_float4(hi[0], hi[1], hi[2], hi[3]);
            *(float4*)(C + (size_t)(r0 + 1) * D2 + bn + tj * 8 + 4) = make_float4(hi[4], hi[5], hi[6], hi[7]);
        }
    }
}

// ---------------- CSR gather aggregation (64-dim), one warp per node ----------------
// out[d] = dinv_d * ( sum_s dinv_s*in[s] + dinv_d*in[d] )  [+bias, relu if RELU]
template <bool RELU>
__global__ __launch_bounds__(256) void k_gather64(const float* __restrict__ in,
                                                  float* __restrict__ out,
                                                  const float* __restrict__ bias) {
    int node = (blockIdx.x * blockDim.x + threadIdx.x) >> 5;
    if (node >= NN) return;
    int lane = threadIdx.x & 31;
    float dd = g_dinv[node];
    float2 self = ((const float2*)(in + (size_t)node * 64))[lane];
    float ax = self.x * dd, ay = self.y * dd;
    int e   = g_rowstart[node];
    int end = g_rowstart[node + 1];
    for (; e + 1 < end; e += 2) {
        int s0 = __ldg(&g_csrsrc[e]);
        int s1 = __ldg(&g_csrsrc[e + 1]);
        float w0 = __ldg(&g_dinv[s0]);
        float w1 = __ldg(&g_dinv[s1]);
        float2 v0 = ((const float2*)(in + (size_t)s0 * 64))[lane];
        float2 v1 = ((const float2*)(in + (size_t)s1 * 64))[lane];
        ax += v0.x * w0 + v1.x * w1;
        ay += v0.y * w0 + v1.y * w1;
    }
    if (e < end) {
        int s = __ldg(&g_csrsrc[e]);
        float w = __ldg(&g_dinv[s]);
        float2 v = ((const float2*)(in + (size_t)s * 64))[lane];
        ax += v.x * w;
        ay += v.y * w;
    }
    ax *= dd; ay *= dd;
    if (RELU) {
        float2 bb = ((const float2*)bias)[lane];
        ax = fmaxf(ax + bb.x, 0.f);
        ay = fmaxf(ay + bb.y, 0.f);
    }
    ((float2*)(out + (size_t)node * 64))[lane] = make_float2(ax, ay);
}

// ---------------- layer 3 ----------------
__global__ __launch_bounds__(256) void k_matvec(const float* __restrict__ H,
                                                const float* __restrict__ W3) {
    int warp = (blockIdx.x * blockDim.x + threadIdx.x) >> 5;
    int lane = threadIdx.x & 31;
    if (warp >= NN) return;
    const float4* row = (const float4*)(H + (size_t)warp * D2);
    const float4* w   = (const float4*)W3;
    float4 a0 = row[lane], a1 = row[lane + 32];
    float4 w0 = w[lane],   w1 = w[lane + 32];
    float s = a0.x * w0.x + a0.y * w0.y + a0.z * w0.z + a0.w * w0.w
            + a1.x * w1.x + a1.y * w1.y + a1.z * w1.z + a1.w * w1.w;
#pragma unroll
    for (int off = 16; off; off >>= 1) s += __shfl_down_sync(0xffffffffu, s, off);
    if (lane == 0) g_z0[warp] = s;
}

__global__ void k_zagg(const float* __restrict__ b3) {
    int i = blockIdx.x * blockDim.x + threadIdx.x;
    if (i >= NN) return;
    float dd  = g_dinv[i];
    float acc = g_z0[i] * dd;
    int e = g_rowstart[i], end = g_rowstart[i + 1];
    for (; e < end; e++) {
        int s = __ldg(&g_csrsrc[e]);
        acc += __ldg(&g_z0[s]) * __ldg(&g_dinv[s]);
    }
    g_z[i] = acc * dd + b3[0];
}

// ---------------- loss ----------------
__global__ void k_zero(float* out) {
    if (blockIdx.x == 0 && threadIdx.x == 0) out[0] = 0.f;
}
__global__ void k_loss(const float* __restrict__ y, float* __restrict__ out) {
    __shared__ float red[256];
    int i = blockIdx.x * blockDim.x + threadIdx.x;
    float v = 0.f;
    if (i < NN) {
        float z = g_z[i];
        float t = y[i];
        v = fmaxf(z, 0.f) - z * t + log1pf(expf(-fabsf(z)));
    }
    red[threadIdx.x] = v;
    __syncthreads();
    for (int s = 128; s > 0; s >>= 1) {
        if (threadIdx.x < s) red[threadIdx.x] += red[threadIdx.x + s];
        __syncthreads();
    }
    if (threadIdx.x == 0) atomicAdd(out, red[0] * (1.0f / NN));
}

// ---------------- launcher ----------------
extern "C" void kernel_launch(void* const* d_in, const int* in_sizes, int n_in,
                              void* d_out, int out_size) {
    const float* x  = (const float*)d_in[0];
    const int*   ei = (const int*)  d_in[1];
    const float* y  = (const float*)d_in[2];
    const float* W1 = (const float*)d_in[3];
    const float* b1 = (const float*)d_in[4];
    const float* W2 = (const float*)d_in[5];
    const float* b2 = (const float*)d_in[6];
    const float* W3 = (const float*)d_in[7];
    const float* b3 = (const float*)d_in[8];
    const int* src = ei;
    const int* dst = ei + NE;
    float* out = (float*)d_out;

    float *p_xw1, *p_h1, *p_ah1, *p_h2;
    cudaGetSymbolAddress((void**)&p_xw1, g_xw1);
    cudaGetSymbolAddress((void**)&p_h1,  g_h1);
    cudaGetSymbolAddress((void**)&p_ah1, g_ah1);
    cudaGetSymbolAddress((void**)&p_h2,  g_h2);

    const int T = 256;
    // ---- CSR build + dinv ----
    k_clear<<<(NN + T - 1) / T, T>>>();
    k_hist <<<(NE + T - 1) / T, T>>>(dst);
    k_scan1<<<SCAN_NB, SCAN_B>>>();
    k_scan2<<<1, 32>>>();
    k_scan3<<<(NN + T - 1) / T, T>>>();
    k_fill <<<(NE + T - 1) / T, T>>>(src, dst);

    // ---- layer 1: xw1 = x@W1 ; h1 = relu(A xw1 + b1) ----
    k_gemm1<<<(NN + 127) / 128, 128>>>(x, W1, p_xw1);
    k_gather64<true><<<(NN * 32 + T - 1) / T, T>>>(p_xw1, p_h1, b1);

    // ---- layer 2: ah1 = A h1 ; h2 = relu(ah1@W2 + b2) ----
    k_gather64<false><<<(NN * 32 + T - 1) / T, T>>>(p_h1, p_ah1, b1);
    dim3 g2((NN + 127) / 128, D2 / 64);
    k_gemm2<<<g2, 128>>>(p_ah1, W2, b2, p_h2);

    // ---- layer 3: z0 = h2@W3 ; z = A z0 + b3 ----
    k_matvec<<<(NN * 32 + T - 1) / T, T>>>(p_h2, W3);
    k_zagg<<<(NN + T - 1) / T, T>>>(b3);

    // ---- loss ----
    k_zero<<<1, 32>>>(out);
    k_loss<<<(NN + T - 1) / T, T>>>(y, out);
}

// round 5
// speedup vs baseline: 1.4382x; 1.0582x over previous
#include <cuda_runtime.h>
#include <stdint.h>
#include <math.h>

#define NN 100000
#define NE 1600000
#define FIN 512
#define D1 64
#define D2 256
#define SCAN_B 1024
#define SCAN_NB ((NN + SCAN_B - 1) / SCAN_B)

typedef unsigned long long ull;

__device__ float g_dinv[NN];
__device__ int   g_cnt[NN];
__device__ int   g_tmp[NN];
__device__ int   g_bsum[SCAN_NB];
__device__ int   g_rowstart[NN + 1];
__device__ int   g_csrsrc[NE];
__device__ float g_xw1[(size_t)NN * D1];
__device__ float g_h1 [(size_t)NN * D1];
__device__ float g_ah1[(size_t)NN * D1];
__device__ float g_z0 [NN];

// ---------------- f32x2 helpers ----------------
__device__ __forceinline__ void ffma2(ull& d, ull a, ull b) {
    asm("fma.rn.f32x2 %0, %1, %2, %0;" : "+l"(d) : "l"(a), "l"(b));
}
__device__ __forceinline__ void unpk2(ull v, float& lo, float& hi) {
    asm("mov.b64 {%0, %1}, %2;" : "=f"(lo), "=f"(hi) : "l"(v));
}

// ---------------- CSR build ----------------
__global__ void k_clear() {
    int i = blockIdx.x * blockDim.x + threadIdx.x;
    if (i < NN) { g_cnt[i] = 0; g_z0[i] = 0.f; }
}
__global__ void k_hist(const int* __restrict__ dst) {
    int e = blockIdx.x * blockDim.x + threadIdx.x;
    if (e < NE) atomicAdd(&g_cnt[dst[e]], 1);
}
__global__ __launch_bounds__(SCAN_B) void k_scan1() {
    __shared__ int sh[SCAN_B];
    int t = threadIdx.x;
    int i = blockIdx.x * SCAN_B + t;
    sh[t] = (i < NN) ? g_cnt[i] : 0;
    __syncthreads();
#pragma unroll
    for (int off = 1; off < SCAN_B; off <<= 1) {
        int v = (t >= off) ? sh[t - off] : 0;
        __syncthreads();
        sh[t] += v;
        __syncthreads();
    }
    if (i < NN) g_tmp[i] = sh[t];
    if (t == SCAN_B - 1) g_bsum[blockIdx.x] = sh[t];
}
// exclusive scan of g_bsum (SCAN_NB <= 128), one block
__global__ __launch_bounds__(128) void k_scan2() {
    __shared__ int sh[128];
    int t = threadIdx.x;
    int v0 = (t < SCAN_NB) ? g_bsum[t] : 0;
    sh[t] = v0;
    __syncthreads();
#pragma unroll
    for (int off = 1; off < 128; off <<= 1) {
        int v = (t >= off) ? sh[t - off] : 0;
        __syncthreads();
        sh[t] += v;
        __syncthreads();
    }
    if (t < SCAN_NB) g_bsum[t] = sh[t] - v0;   // exclusive
}
__global__ void k_scan3() {
    int i = blockIdx.x * blockDim.x + threadIdx.x;
    if (i < NN) {
        g_rowstart[i + 1] = g_tmp[i] + g_bsum[i >> 10];
        if (i == 0) g_rowstart[0] = 0;
        int c = g_cnt[i];
        g_dinv[i] = rsqrtf((float)c + 1.0f);
        g_cnt[i] = 0;
    }
}
__global__ void k_fill(const int* __restrict__ src, const int* __restrict__ dst) {
    int e = blockIdx.x * blockDim.x + threadIdx.x;
    if (e < NE) {
        int d = dst[e];
        int pos = g_rowstart[d] + atomicAdd(&g_cnt[d], 1);
        g_csrsrc[pos] = src[e];
    }
}

// ---------------- GEMM1: C[M,64] = A[M,512] @ B[512,64]  (f32x2) ----------------
__global__ __launch_bounds__(128) void k_gemm1(const float* __restrict__ A,
                                               const float* __restrict__ B,
                                               float* __restrict__ C) {
    __shared__ float As[32][132];    // transposed: As[k][m]
    __shared__ float Bs2[32][132];   // duplicated: Bs2[k][2j]=Bs2[k][2j+1]=B[k][j]
    int tid = threadIdx.x;
    int bm  = blockIdx.x * 128;
    int ti  = tid & 15;   // 8 rows each (4 pairs)
    int tj  = tid >> 4;   // 8 cols each
    ull accp[4][8];
#pragma unroll
    for (int p = 0; p < 4; p++)
#pragma unroll
        for (int j = 0; j < 8; j++) accp[p][j] = 0ull;

    int gr = bm + tid;
    bool valid = gr < NN;

    for (int k0 = 0; k0 < FIN; k0 += 32) {
#pragma unroll
        for (int kk = 0; kk < 8; kk++) {
            float4 v = valid ? *(const float4*)(A + (size_t)gr * FIN + k0 + kk * 4)
                             : make_float4(0.f, 0.f, 0.f, 0.f);
            As[kk * 4 + 0][tid] = v.x;
            As[kk * 4 + 1][tid] = v.y;
            As[kk * 4 + 2][tid] = v.z;
            As[kk * 4 + 3][tid] = v.w;
        }
#pragma unroll
        for (int it = 0; it < 4; it++) {
            int kr = it * 8 + (tid >> 4);
            int nc = (tid & 15) * 4;
            float4 v = *(const float4*)(B + (size_t)(k0 + kr) * 64 + nc);
            float2* brow = (float2*)&Bs2[kr][nc * 2];
            brow[0] = make_float2(v.x, v.x);
            brow[1] = make_float2(v.y, v.y);
            brow[2] = make_float2(v.z, v.z);
            brow[3] = make_float2(v.w, v.w);
        }
        __syncthreads();
#pragma unroll
        for (int k = 0; k < 32; k++) {
            const ulonglong2* ap = (const ulonglong2*)&As[k][ti * 8];
            ulonglong2 a01 = ap[0], a23 = ap[1];
            ull pa[4] = {a01.x, a01.y, a23.x, a23.y};
            const ulonglong2* bp = (const ulonglong2*)&Bs2[k][tj * 16];
            ulonglong2 b0 = bp[0], b1 = bp[1], b2 = bp[2], b3 = bp[3];
            ull pb[8] = {b0.x, b0.y, b1.x, b1.y, b2.x, b2.y, b3.x, b3.y};
#pragma unroll
            for (int p = 0; p < 4; p++)
#pragma unroll
                for (int j = 0; j < 8; j++) ffma2(accp[p][j], pa[p], pb[j]);
        }
        __syncthreads();
    }
#pragma unroll
    for (int p = 0; p < 4; p++) {
        float lo[8], hi[8];
#pragma unroll
        for (int j = 0; j < 8; j++) unpk2(accp[p][j], lo[j], hi[j]);
        int r0 = bm + ti * 8 + 2 * p;
        if (r0 < NN) {
            *(float4*)(C + (size_t)r0 * 64 + tj * 8)     = make_float4(lo[0], lo[1], lo[2], lo[3]);
            *(float4*)(C + (size_t)r0 * 64 + tj * 8 + 4) = make_float4(lo[4], lo[5], lo[6], lo[7]);
        }
        if (r0 + 1 < NN) {
            *(float4*)(C + (size_t)(r0 + 1) * 64 + tj * 8)     = make_float4(hi[0], hi[1], hi[2], hi[3]);
            *(float4*)(C + (size_t)(r0 + 1) * 64 + tj * 8 + 4) = make_float4(hi[4], hi[5], hi[6], hi[7]);
        }
    }
}

// ---------------- GEMM2 fused with W3 matvec: accumulates z0 (f32x2) ----------------
__global__ __launch_bounds__(128) void k_gemm2(const float* __restrict__ A,
                                               const float* __restrict__ B,
                                               const float* __restrict__ bias,
                                               const float* __restrict__ W3) {
    __shared__ float As[32][132];
    __shared__ float Bs2[32][132];
    __shared__ float zpart[128];
    int tid = threadIdx.x;
    int bm  = blockIdx.x * 128;
    int bn  = blockIdx.y * 64;
    int ti  = tid & 15;
    int tj  = tid >> 4;
    zpart[tid] = 0.f;
    ull accp[4][8];
#pragma unroll
    for (int p = 0; p < 4; p++)
#pragma unroll
        for (int j = 0; j < 8; j++) accp[p][j] = 0ull;

    int gr = bm + tid;
    bool valid = gr < NN;

    for (int k0 = 0; k0 < D1; k0 += 32) {
#pragma unroll
        for (int kk = 0; kk < 8; kk++) {
            float4 v = valid ? *(const float4*)(A + (size_t)gr * D1 + k0 + kk * 4)
                             : make_float4(0.f, 0.f, 0.f, 0.f);
            As[kk * 4 + 0][tid] = v.x;
            As[kk * 4 + 1][tid] = v.y;
            As[kk * 4 + 2][tid] = v.z;
            As[kk * 4 + 3][tid] = v.w;
        }
#pragma unroll
        for (int it = 0; it < 4; it++) {
            int kr = it * 8 + (tid >> 4);
            int nc = (tid & 15) * 4;
            float4 v = *(const float4*)(B + (size_t)(k0 + kr) * D2 + bn + nc);
            float2* brow = (float2*)&Bs2[kr][nc * 2];
            brow[0] = make_float2(v.x, v.x);
            brow[1] = make_float2(v.y, v.y);
            brow[2] = make_float2(v.z, v.z);
            brow[3] = make_float2(v.w, v.w);
        }
        __syncthreads();
#pragma unroll
        for (int k = 0; k < 32; k++) {
            const ulonglong2* ap = (const ulonglong2*)&As[k][ti * 8];
            ulonglong2 a01 = ap[0], a23 = ap[1];
            ull pa[4] = {a01.x, a01.y, a23.x, a23.y};
            const ulonglong2* bp = (const ulonglong2*)&Bs2[k][tj * 16];
            ulonglong2 b0 = bp[0], b1 = bp[1], b2 = bp[2], b3 = bp[3];
            ull pb[8] = {b0.x, b0.y, b1.x, b1.y, b2.x, b2.y, b3.x, b3.y};
#pragma unroll
            for (int p = 0; p < 4; p++)
#pragma unroll
                for (int j = 0; j < 8; j++) ffma2(accp[p][j], pa[p], pb[j]);
        }
        __syncthreads();
    }
    float4 bb0 = *(const float4*)&bias[bn + tj * 8];
    float4 bb1 = *(const float4*)&bias[bn + tj * 8 + 4];
    float bv[8] = {bb0.x, bb0.y, bb0.z, bb0.w, bb1.x, bb1.y, bb1.z, bb1.w};
    float4 ww0 = *(const float4*)&W3[bn + tj * 8];
    float4 ww1 = *(const float4*)&W3[bn + tj * 8 + 4];
    float wv[8] = {ww0.x, ww0.y, ww0.z, ww0.w, ww1.x, ww1.y, ww1.z, ww1.w};
#pragma unroll
    for (int p = 0; p < 4; p++) {
        float lo[8], hi[8];
        float slo = 0.f, shi = 0.f;
#pragma unroll
        for (int j = 0; j < 8; j++) {
            unpk2(accp[p][j], lo[j], hi[j]);
            lo[j] = fmaxf(lo[j] + bv[j], 0.f);
            hi[j] = fmaxf(hi[j] + bv[j], 0.f);
            slo += lo[j] * wv[j];
            shi += hi[j] * wv[j];
        }
        int rl = ti * 8 + 2 * p;
        atomicAdd(&zpart[rl],     slo);
        atomicAdd(&zpart[rl + 1], shi);
    }
    __syncthreads();
    if (bm + tid < NN) atomicAdd(&g_z0[bm + tid], zpart[tid]);
}

// ---------------- CSR gather aggregation (64-dim), one warp per node ----------------
template <bool RELU>
__global__ __launch_bounds__(256) void k_gather64(const float* __restrict__ in,
                                                  float* __restrict__ out,
                                                  const float* __restrict__ bias) {
    int node = (blockIdx.x * blockDim.x + threadIdx.x) >> 5;
    if (node >= NN) return;
    int lane = threadIdx.x & 31;
    float dd = g_dinv[node];
    float2 self = ((const float2*)(in + (size_t)node * 64))[lane];
    float ax = self.x * dd, ay = self.y * dd;
    int e   = g_rowstart[node];
    int end = g_rowstart[node + 1];
    for (; e + 1 < end; e += 2) {
        int s0 = __ldg(&g_csrsrc[e]);
        int s1 = __ldg(&g_csrsrc[e + 1]);
        float w0 = __ldg(&g_dinv[s0]);
        float w1 = __ldg(&g_dinv[s1]);
        float2 v0 = ((const float2*)(in + (size_t)s0 * 64))[lane];
        float2 v1 = ((const float2*)(in + (size_t)s1 * 64))[lane];
        ax += v0.x * w0 + v1.x * w1;
        ay += v0.y * w0 + v1.y * w1;
    }
    if (e < end) {
        int s = __ldg(&g_csrsrc[e]);
        float w = __ldg(&g_dinv[s]);
        float2 v = ((const float2*)(in + (size_t)s * 64))[lane];
        ax += v.x * w;
        ay += v.y * w;
    }
    ax *= dd; ay *= dd;
    if (RELU) {
        float2 bb = ((const float2*)bias)[lane];
        ax = fmaxf(ax + bb.x, 0.f);
        ay = fmaxf(ay + bb.y, 0.f);
    }
    ((float2*)(out + (size_t)node * 64))[lane] = make_float2(ax, ay);
}

// ---------------- fused z aggregation + BCE loss ----------------
__global__ void k_zero(float* out) {
    if (blockIdx.x == 0 && threadIdx.x == 0) out[0] = 0.f;
}
__global__ __launch_bounds__(256) void k_zagg_loss(const float* __restrict__ b3,
                                                   const float* __restrict__ y,
                                                   float* __restrict__ out) {
    __shared__ float red[256];
    int i = blockIdx.x * blockDim.x + threadIdx.x;
    float v = 0.f;
    if (i < NN) {
        float dd  = g_dinv[i];
        float acc = g_z0[i] * dd;
        int e = g_rowstart[i], end = g_rowstart[i + 1];
        for (; e < end; e++) {
            int s = __ldg(&g_csrsrc[e]);
            acc += __ldg(&g_z0[s]) * __ldg(&g_dinv[s]);
        }
        float z = acc * dd + b3[0];
        float t = y[i];
        v = fmaxf(z, 0.f) - z * t + log1pf(expf(-fabsf(z)));
    }
    red[threadIdx.x] = v;
    __syncthreads();
    for (int s = 128; s > 0; s >>= 1) {
        if (threadIdx.x < s) red[threadIdx.x] += red[threadIdx.x + s];
        __syncthreads();
    }
    if (threadIdx.x == 0) atomicAdd(out, red[0] * (1.0f / NN));
}

// ---------------- launcher ----------------
extern "C" void kernel_launch(void* const* d_in, const int* in_sizes, int n_in,
                              void* d_out, int out_size) {
    const float* x  = (const float*)d_in[0];
    const int*   ei = (const int*)  d_in[1];
    const float* y  = (const float*)d_in[2];
    const float* W1 = (const float*)d_in[3];
    const float* b1 = (const float*)d_in[4];
    const float* W2 = (const float*)d_in[5];
    const float* b2 = (const float*)d_in[6];
    const float* W3 = (const float*)d_in[7];
    const float* b3 = (const float*)d_in[8];
    const int* src = ei;
    const int* dst = ei + NE;
    float* out = (float*)d_out;

    float *p_xw1, *p_h1, *p_ah1;
    cudaGetSymbolAddress((void**)&p_xw1, g_xw1);
    cudaGetSymbolAddress((void**)&p_h1,  g_h1);
    cudaGetSymbolAddress((void**)&p_ah1, g_ah1);

    const int T = 256;
    // ---- CSR build + dinv (also zeroes z0 accumulators) ----
    k_clear<<<(NN + T - 1) / T, T>>>();
    k_hist <<<(NE + T - 1) / T, T>>>(dst);
    k_scan1<<<SCAN_NB, SCAN_B>>>();
    k_scan2<<<1, 128>>>();
    k_scan3<<<(NN + T - 1) / T, T>>>();
    k_fill <<<(NE + T - 1) / T, T>>>(src, dst);

    // ---- layer 1 ----
    k_gemm1<<<(NN + 127) / 128, 128>>>(x, W1, p_xw1);
    k_gather64<true><<<(NN * 32 + T - 1) / T, T>>>(p_xw1, p_h1, b1);

    // ---- layer 2 + fused layer-3 matvec ----
    k_gather64<false><<<(NN * 32 + T - 1) / T, T>>>(p_h1, p_ah1, b1);
    dim3 g2((NN + 127) / 128, D2 / 64);
    k_gemm2<<<g2, 128>>>(p_ah1, W2, b2, W3);

    // ---- z aggregation + loss ----
    k_zero<<<1, 32>>>(out);
    k_zagg_loss<<<(NN + T - 1) / T, T>>>(b3, y, out);
}

// round 6
// speedup vs baseline: 1.9206x; 1.3354x over previous
#include <cuda_runtime.h>
#include <cuda_bf16.h>
#include <stdint.h>
#include <math.h>

#define NN 100000
#define NE 1600000
#define FIN 512
#define D1 64
#define D2 256
#define SCAN_B 1024
#define SCAN_NB ((NN + SCAN_B - 1) / SCAN_B)

typedef unsigned long long ull;

__device__ float g_dinv[NN];
__device__ int   g_cnt[NN];
__device__ int   g_tmp[NN];
__device__ int   g_bsum[SCAN_NB];
__device__ int   g_rowstart[NN + 1];
__device__ int   g_csrsrc[NE];
__device__ uint4 g_bfrag[8192];            // packed W1 b-fragments: [kstep 32][ntile 8][lane 32]
__device__ float g_xw1[(size_t)NN * D1];
__device__ float g_h1 [(size_t)NN * D1];
__device__ float g_ah1[(size_t)NN * D1];
__device__ float g_z0 [NN];

// ---------------- f32x2 helpers ----------------
__device__ __forceinline__ void ffma2(ull& d, ull a, ull b) {
    asm("fma.rn.f32x2 %0, %1, %2, %0;" : "+l"(d) : "l"(a), "l"(b));
}
__device__ __forceinline__ void unpk2(ull v, float& lo, float& hi) {
    asm("mov.b64 {%0, %1}, %2;" : "=f"(lo), "=f"(hi) : "l"(v));
}

// ---------------- bf16 helpers ----------------
__device__ __forceinline__ uint32_t pkbf(float a, float b) {   // a -> low 16, b -> high 16
    __nv_bfloat162 h = __floats2bfloat162_rn(a, b);
    return *(uint32_t*)&h;
}
__device__ __forceinline__ float bfres(float f) {              // residual after bf16 rounding
    return f - __bfloat162float(__float2bfloat16(f));
}
__device__ __forceinline__ void mma_bf16(float* c, const uint32_t* a, uint32_t b0, uint32_t b1) {
    asm("mma.sync.aligned.m16n8k16.row.col.f32.bf16.bf16.f32 "
        "{%0,%1,%2,%3}, {%4,%5,%6,%7}, {%8,%9}, {%0,%1,%2,%3};"
        : "+f"(c[0]), "+f"(c[1]), "+f"(c[2]), "+f"(c[3])
        : "r"(a[0]), "r"(a[1]), "r"(a[2]), "r"(a[3]), "r"(b0), "r"(b1));
}

// ---------------- CSR build ----------------
__global__ void k_clear() {
    int i = blockIdx.x * blockDim.x + threadIdx.x;
    if (i < NN) { g_cnt[i] = 0; g_z0[i] = 0.f; }
}
__global__ void k_hist(const int* __restrict__ dst) {
    int e = blockIdx.x * blockDim.x + threadIdx.x;
    if (e < NE) atomicAdd(&g_cnt[dst[e]], 1);
}
__global__ __launch_bounds__(SCAN_B) void k_scan1() {
    __shared__ int sh[SCAN_B];
    int t = threadIdx.x;
    int i = blockIdx.x * SCAN_B + t;
    sh[t] = (i < NN) ? g_cnt[i] : 0;
    __syncthreads();
#pragma unroll
    for (int off = 1; off < SCAN_B; off <<= 1) {
        int v = (t >= off) ? sh[t - off] : 0;
        __syncthreads();
        sh[t] += v;
        __syncthreads();
    }
    if (i < NN) g_tmp[i] = sh[t];
    if (t == SCAN_B - 1) g_bsum[blockIdx.x] = sh[t];
}
__global__ __launch_bounds__(128) void k_scan2() {
    __shared__ int sh[128];
    int t = threadIdx.x;
    int v0 = (t < SCAN_NB) ? g_bsum[t] : 0;
    sh[t] = v0;
    __syncthreads();
#pragma unroll
    for (int off = 1; off < 128; off <<= 1) {
        int v = (t >= off) ? sh[t - off] : 0;
        __syncthreads();
        sh[t] += v;
        __syncthreads();
    }
    if (t < SCAN_NB) g_bsum[t] = sh[t] - v0;   // exclusive
}
__global__ void k_scan3() {
    int i = blockIdx.x * blockDim.x + threadIdx.x;
    if (i < NN) {
        g_rowstart[i + 1] = g_tmp[i] + g_bsum[i >> 10];
        if (i == 0) g_rowstart[0] = 0;
        int c = g_cnt[i];
        g_dinv[i] = rsqrtf((float)c + 1.0f);
        g_cnt[i] = 0;
    }
}
__global__ void k_fill(const int* __restrict__ src, const int* __restrict__ dst) {
    int e = blockIdx.x * blockDim.x + threadIdx.x;
    if (e < NE) {
        int d = dst[e];
        int pos = g_rowstart[d] + atomicAdd(&g_cnt[d], 1);
        g_csrsrc[pos] = src[e];
    }
}

// ---------------- pack W1 into mma b-fragments (hi/lo split) ----------------
// b-frag (m16n8k16, col B): lane l (g=l>>2,t=l&3): b0={B[k+2t][n], B[k+2t+1][n]}, b1={B[k+2t+8][n], B[k+2t+9][n]}
__global__ void k_packB(const float* __restrict__ B) {
    int e = blockIdx.x * blockDim.x + threadIdx.x;
    if (e >= 8192) return;
    int l = e & 31, j = (e >> 5) & 7, s = e >> 8;
    int g = l >> 2, t = l & 3;
    int n = 8 * j + g;
    int k = 16 * s + 2 * t;
    float f0 = B[(size_t)k * 64 + n];
    float f1 = B[(size_t)(k + 1) * 64 + n];
    float f2 = B[(size_t)(k + 8) * 64 + n];
    float f3 = B[(size_t)(k + 9) * 64 + n];
    uint32_t h01 = pkbf(f0, f1);
    uint32_t h23 = pkbf(f2, f3);
    uint32_t l01 = pkbf(bfres(f0), bfres(f1));
    uint32_t l23 = pkbf(bfres(f2), bfres(f3));
    g_bfrag[e] = make_uint4(h01, h23, l01, l23);
}

// ---------------- GEMM1 via mma.sync bf16 split-3: C[M,64] = A[M,512] @ W1 ----------------
// M-tile 256, 8 warps x 32 rows. smem: Ahi/Alo [256][72] bf16 (stride pad for conflict-free frags).
#define G1A_STRIDE 36                         // uint32 (bf16 pairs) per row
#define G1_SMEM_BYTES (2 * 256 * 72 * 2)      // 73728
__global__ __launch_bounds__(256) void k_gemm1_mma(const float* __restrict__ A,
                                                   float* __restrict__ C) {
    extern __shared__ char smem[];
    uint32_t* Ah = (uint32_t*)smem;                     // 256 x 36 uint32
    uint32_t* Al = (uint32_t*)(smem + 256 * 72 * 2);
    int tid  = threadIdx.x;
    int lane = tid & 31;
    int w    = tid >> 5;
    int g    = lane >> 2;
    int t    = lane & 3;
    int bm   = blockIdx.x * 256;

    float acc[2][8][4];
#pragma unroll
    for (int m = 0; m < 2; m++)
#pragma unroll
        for (int j = 0; j < 8; j++)
#pragma unroll
            for (int q = 0; q < 4; q++) acc[m][j][q] = 0.f;

    int lr = tid >> 4;            // 0..15
    int c4 = (tid & 15) * 4;      // float col within 64-chunk

    for (int ch = 0; ch < 8; ch++) {
        int k0 = ch * 64;
        // ---- stage A chunk (fp32 -> bf16 hi/lo) ----
#pragma unroll
        for (int i = 0; i < 16; i++) {
            int row  = lr + 16 * i;
            int grow = bm + row;
            float4 v = (grow < NN) ? *(const float4*)(A + (size_t)grow * FIN + k0 + c4)
                                   : make_float4(0.f, 0.f, 0.f, 0.f);
            uint32_t h01 = pkbf(v.x, v.y);
            uint32_t h23 = pkbf(v.z, v.w);
            uint32_t l01 = pkbf(bfres(v.x), bfres(v.y));
            uint32_t l23 = pkbf(bfres(v.z), bfres(v.w));
            int idx = row * G1A_STRIDE + (c4 >> 1);
            *(uint2*)&Ah[idx] = make_uint2(h01, h23);
            *(uint2*)&Al[idx] = make_uint2(l01, l23);
        }
        __syncthreads();
        // ---- 4 k-steps of 16 ----
#pragma unroll
        for (int s4 = 0; s4 < 4; s4++) {
            int kk = s4 * 16;
            int gs = ch * 4 + s4;                 // global k-step 0..31
            uint32_t ah[2][4], al[2][4];
#pragma unroll
            for (int m = 0; m < 2; m++) {
                int r0 = w * 32 + m * 16 + g;
                int kc = (kk + 2 * t) >> 1;
                ah[m][0] = Ah[r0 * G1A_STRIDE + kc];
                ah[m][1] = Ah[(r0 + 8) * G1A_STRIDE + kc];
                ah[m][2] = Ah[r0 * G1A_STRIDE + kc + 4];
                ah[m][3] = Ah[(r0 + 8) * G1A_STRIDE + kc + 4];
                al[m][0] = Al[r0 * G1A_STRIDE + kc];
                al[m][1] = Al[(r0 + 8) * G1A_STRIDE + kc];
                al[m][2] = Al[r0 * G1A_STRIDE + kc + 4];
                al[m][3] = Al[(r0 + 8) * G1A_STRIDE + kc + 4];
            }
#pragma unroll
            for (int j = 0; j < 8; j++) {
                uint4 bf4 = __ldg(&g_bfrag[(gs * 8 + j) * 32 + lane]);
#pragma unroll
                for (int m = 0; m < 2; m++) {
                    mma_bf16(acc[m][j], ah[m], bf4.x, bf4.y);   // Ahi*Bhi
                    mma_bf16(acc[m][j], ah[m], bf4.z, bf4.w);   // Ahi*Blo
                    mma_bf16(acc[m][j], al[m], bf4.x, bf4.y);   // Alo*Bhi
                }
            }
        }
        __syncthreads();
    }
    // ---- epilogue ----
#pragma unroll
    for (int m = 0; m < 2; m++) {
        int row = bm + w * 32 + m * 16 + g;
#pragma unroll
        for (int j = 0; j < 8; j++) {
            int col = 8 * j + 2 * t;
            if (row < NN)
                *(float2*)(C + (size_t)row * 64 + col) = make_float2(acc[m][j][0], acc[m][j][1]);
            if (row + 8 < NN)
                *(float2*)(C + (size_t)(row + 8) * 64 + col) = make_float2(acc[m][j][2], acc[m][j][3]);
        }
    }
}

// ---------------- GEMM2 fused with W3 matvec: accumulates z0 (f32x2) ----------------
__global__ __launch_bounds__(128) void k_gemm2(const float* __restrict__ A,
                                               const float* __restrict__ B,
                                               const float* __restrict__ bias,
                                               const float* __restrict__ W3) {
    __shared__ float As[32][132];
    __shared__ float Bs2[32][132];
    __shared__ float zpart[128];
    int tid = threadIdx.x;
    int bm  = blockIdx.x * 128;
    int bn  = blockIdx.y * 64;
    int ti  = tid & 15;
    int tj  = tid >> 4;
    zpart[tid] = 0.f;
    ull accp[4][8];
#pragma unroll
    for (int p = 0; p < 4; p++)
#pragma unroll
        for (int j = 0; j < 8; j++) accp[p][j] = 0ull;

    int gr = bm + tid;
    bool valid = gr < NN;

    for (int k0 = 0; k0 < D1; k0 += 32) {
#pragma unroll
        for (int kk = 0; kk < 8; kk++) {
            float4 v = valid ? *(const float4*)(A + (size_t)gr * D1 + k0 + kk * 4)
                             : make_float4(0.f, 0.f, 0.f, 0.f);
            As[kk * 4 + 0][tid] = v.x;
            As[kk * 4 + 1][tid] = v.y;
            As[kk * 4 + 2][tid] = v.z;
            As[kk * 4 + 3][tid] = v.w;
        }
#pragma unroll
        for (int it = 0; it < 4; it++) {
            int kr = it * 8 + (tid >> 4);
            int nc = (tid & 15) * 4;
            float4 v = *(const float4*)(B + (size_t)(k0 + kr) * D2 + bn + nc);
            float2* brow = (float2*)&Bs2[kr][nc * 2];
            brow[0] = make_float2(v.x, v.x);
            brow[1] = make_float2(v.y, v.y);
            brow[2] = make_float2(v.z, v.z);
            brow[3] = make_float2(v.w, v.w);
        }
        __syncthreads();
#pragma unroll
        for (int k = 0; k < 32; k++) {
            const ulonglong2* ap = (const ulonglong2*)&As[k][ti * 8];
            ulonglong2 a01 = ap[0], a23 = ap[1];
            ull pa[4] = {a01.x, a01.y, a23.x, a23.y};
            const ulonglong2* bp = (const ulonglong2*)&Bs2[k][tj * 16];
            ulonglong2 b0 = bp[0], b1 = bp[1], b2 = bp[2], b3 = bp[3];
            ull pb[8] = {b0.x, b0.y, b1.x, b1.y, b2.x, b2.y, b3.x, b3.y};
#pragma unroll
            for (int p = 0; p < 4; p++)
#pragma unroll
                for (int j = 0; j < 8; j++) ffma2(accp[p][j], pa[p], pb[j]);
        }
        __syncthreads();
    }
    float4 bb0 = *(const float4*)&bias[bn + tj * 8];
    float4 bb1 = *(const float4*)&bias[bn + tj * 8 + 4];
    float bv[8] = {bb0.x, bb0.y, bb0.z, bb0.w, bb1.x, bb1.y, bb1.z, bb1.w};
    float4 ww0 = *(const float4*)&W3[bn + tj * 8];
    float4 ww1 = *(const float4*)&W3[bn + tj * 8 + 4];
    float wv[8] = {ww0.x, ww0.y, ww0.z, ww0.w, ww1.x, ww1.y, ww1.z, ww1.w};
#pragma unroll
    for (int p = 0; p < 4; p++) {
        float lo[8], hi[8];
        float slo = 0.f, shi = 0.f;
#pragma unroll
        for (int j = 0; j < 8; j++) {
            unpk2(accp[p][j], lo[j], hi[j]);
            lo[j] = fmaxf(lo[j] + bv[j], 0.f);
            hi[j] = fmaxf(hi[j] + bv[j], 0.f);
            slo += lo[j] * wv[j];
            shi += hi[j] * wv[j];
        }
        int rl = ti * 8 + 2 * p;
        atomicAdd(&zpart[rl],     slo);
        atomicAdd(&zpart[rl + 1], shi);
    }
    __syncthreads();
    if (bm + tid < NN) atomicAdd(&g_z0[bm + tid], zpart[tid]);
}

// ---------------- CSR gather aggregation (64-dim), one warp per node ----------------
template <bool RELU>
__global__ __launch_bounds__(256) void k_gather64(const float* __restrict__ in,
                                                  float* __restrict__ out,
                                                  const float* __restrict__ bias) {
    int node = (blockIdx.x * blockDim.x + threadIdx.x) >> 5;
    if (node >= NN) return;
    int lane = threadIdx.x & 31;
    float dd = g_dinv[node];
    float2 self = ((const float2*)(in + (size_t)node * 64))[lane];
    float ax = self.x * dd, ay = self.y * dd;
    int e   = g_rowstart[node];
    int end = g_rowstart[node + 1];
    for (; e + 1 < end; e += 2) {
        int s0 = __ldg(&g_csrsrc[e]);
        int s1 = __ldg(&g_csrsrc[e + 1]);
        float w0 = __ldg(&g_dinv[s0]);
        float w1 = __ldg(&g_dinv[s1]);
        float2 v0 = ((const float2*)(in + (size_t)s0 * 64))[lane];
        float2 v1 = ((const float2*)(in + (size_t)s1 * 64))[lane];
        ax += v0.x * w0 + v1.x * w1;
        ay += v0.y * w0 + v1.y * w1;
    }
    if (e < end) {
        int s = __ldg(&g_csrsrc[e]);
        float w = __ldg(&g_dinv[s]);
        float2 v = ((const float2*)(in + (size_t)s * 64))[lane];
        ax += v.x * w;
        ay += v.y * w;
    }
    ax *= dd; ay *= dd;
    if (RELU) {
        float2 bb = ((const float2*)bias)[lane];
        ax = fmaxf(ax + bb.x, 0.f);
        ay = fmaxf(ay + bb.y, 0.f);
    }
    ((float2*)(out + (size_t)node * 64))[lane] = make_float2(ax, ay);
}

// ---------------- fused z aggregation + BCE loss ----------------
__global__ void k_zero(float* out) {
    if (blockIdx.x == 0 && threadIdx.x == 0) out[0] = 0.f;
}
__global__ __launch_bounds__(256) void k_zagg_loss(const float* __restrict__ b3,
                                                   const float* __restrict__ y,
                                                   float* __restrict__ out) {
    __shared__ float red[256];
    int i = blockIdx.x * blockDim.x + threadIdx.x;
    float v = 0.f;
    if (i < NN) {
        float dd  = g_dinv[i];
        float acc = g_z0[i] * dd;
        int e = g_rowstart[i], end = g_rowstart[i + 1];
        for (; e < end; e++) {
            int s = __ldg(&g_csrsrc[e]);
            acc += __ldg(&g_z0[s]) * __ldg(&g_dinv[s]);
        }
        float z = acc * dd + b3[0];
        float t = y[i];
        v = fmaxf(z, 0.f) - z * t + log1pf(expf(-fabsf(z)));
    }
    red[threadIdx.x] = v;
    __syncthreads();
    for (int s = 128; s > 0; s >>= 1) {
        if (threadIdx.x < s) red[threadIdx.x] += red[threadIdx.x + s];
        __syncthreads();
    }
    if (threadIdx.x == 0) atomicAdd(out, red[0] * (1.0f / NN));
}

// ---------------- launcher ----------------
extern "C" void kernel_launch(void* const* d_in, const int* in_sizes, int n_in,
                              void* d_out, int out_size) {
    const float* x  = (const float*)d_in[0];
    const int*   ei = (const int*)  d_in[1];
    const float* y  = (const float*)d_in[2];
    const float* W1 = (const float*)d_in[3];
    const float* b1 = (const float*)d_in[4];
    const float* W2 = (const float*)d_in[5];
    const float* b2 = (const float*)d_in[6];
    const float* W3 = (const float*)d_in[7];
    const float* b3 = (const float*)d_in[8];
    const int* src = ei;
    const int* dst = ei + NE;
    float* out = (float*)d_out;

    float *p_xw1, *p_h1, *p_ah1;
    cudaGetSymbolAddress((void**)&p_xw1, g_xw1);
    cudaGetSymbolAddress((void**)&p_h1,  g_h1);
    cudaGetSymbolAddress((void**)&p_ah1, g_ah1);

    cudaFuncSetAttribute(k_gemm1_mma, cudaFuncAttributeMaxDynamicSharedMemorySize, G1_SMEM_BYTES);

    const int T = 256;
    // ---- CSR build + dinv (also zeroes z0 accumulators) + W1 fragment pack ----
    k_clear<<<(NN + T - 1) / T, T>>>();
    k_packB<<<32, 256>>>(W1);
    k_hist <<<(NE + T - 1) / T, T>>>(dst);
    k_scan1<<<SCAN_NB, SCAN_B>>>();
    k_scan2<<<1, 128>>>();
    k_scan3<<<(NN + T - 1) / T, T>>>();
    k_fill <<<(NE + T - 1) / T, T>>>(src, dst);

    // ---- layer 1 ----
    k_gemm1_mma<<<(NN + 255) / 256, 256, G1_SMEM_BYTES>>>(x, p_xw1);
    k_gather64<true><<<(NN * 32 + T - 1) / T, T>>>(p_xw1, p_h1, b1);

    // ---- layer 2 + fused layer-3 matvec ----
    k_gather64<false><<<(NN * 32 + T - 1) / T, T>>>(p_h1, p_ah1, b1);
    dim3 g2((NN + 127) / 128, D2 / 64);
    k_gemm2<<<g2, 128>>>(p_ah1, W2, b2, W3);

    // ---- z aggregation + loss ----
    k_zero<<<1, 32>>>(out);
    k_zagg_loss<<<(NN + T - 1) / T, T>>>(b3, y, out);
}

// round 7
// speedup vs baseline: 2.2822x; 1.1883x over previous
#include <cuda_runtime.h>
#include <cuda_bf16.h>
#include <stdint.h>
#include <math.h>

#define NN 100000
#define NE 1600000
#define FIN 512
#define D1 64
#define D2 256
#define SCAN_B 1024
#define SCAN_NB ((NN + SCAN_B - 1) / SCAN_B)

typedef unsigned long long ull;

__device__ float g_dinv[NN];
__device__ int   g_cnt[NN];
__device__ int   g_tmp[NN];
__device__ int   g_bsum[SCAN_NB];
__device__ int   g_rowstart[NN + 1];
__device__ int   g_csrsrc[NE];
__device__ uint4 g_bfrag[8192];            // packed W1 b-frags: [kstep 32][ntile 8][lane 32]
__device__ uint4 g_bfrag2[4096];           // packed W2 b-frags: [kstep 4][ntile 32][lane 32]
__device__ float g_xw1[(size_t)NN * D1];
__device__ float g_h1 [(size_t)NN * D1];
__device__ float g_ah1[(size_t)NN * D1];
__device__ float g_z0 [NN];

// ---------------- bf16 helpers ----------------
__device__ __forceinline__ uint32_t pkbf(float a, float b) {   // a -> low 16, b -> high 16
    __nv_bfloat162 h = __floats2bfloat162_rn(a, b);
    return *(uint32_t*)&h;
}
__device__ __forceinline__ float bfres(float f) {              // residual after bf16 rounding
    return f - __bfloat162float(__float2bfloat16(f));
}
__device__ __forceinline__ void mma_bf16(float* c, const uint32_t* a, uint32_t b0, uint32_t b1) {
    asm("mma.sync.aligned.m16n8k16.row.col.f32.bf16.bf16.f32 "
        "{%0,%1,%2,%3}, {%4,%5,%6,%7}, {%8,%9}, {%0,%1,%2,%3};"
        : "+f"(c[0]), "+f"(c[1]), "+f"(c[2]), "+f"(c[3])
        : "r"(a[0]), "r"(a[1]), "r"(a[2]), "r"(a[3]), "r"(b0), "r"(b1));
}

// ---------------- CSR build ----------------
__global__ void k_clear() {
    int i = blockIdx.x * blockDim.x + threadIdx.x;
    if (i < NN) { g_cnt[i] = 0; g_z0[i] = 0.f; }
}
__global__ void k_hist(const int* __restrict__ dst) {
    int e = blockIdx.x * blockDim.x + threadIdx.x;
    if (e < NE) atomicAdd(&g_cnt[dst[e]], 1);
}
__global__ __launch_bounds__(SCAN_B) void k_scan1() {
    __shared__ int sh[SCAN_B];
    int t = threadIdx.x;
    int i = blockIdx.x * SCAN_B + t;
    sh[t] = (i < NN) ? g_cnt[i] : 0;
    __syncthreads();
#pragma unroll
    for (int off = 1; off < SCAN_B; off <<= 1) {
        int v = (t >= off) ? sh[t - off] : 0;
        __syncthreads();
        sh[t] += v;
        __syncthreads();
    }
    if (i < NN) g_tmp[i] = sh[t];
    if (t == SCAN_B - 1) g_bsum[blockIdx.x] = sh[t];
}
__global__ __launch_bounds__(128) void k_scan2() {
    __shared__ int sh[128];
    int t = threadIdx.x;
    int v0 = (t < SCAN_NB) ? g_bsum[t] : 0;
    sh[t] = v0;
    __syncthreads();
#pragma unroll
    for (int off = 1; off < 128; off <<= 1) {
        int v = (t >= off) ? sh[t - off] : 0;
        __syncthreads();
        sh[t] += v;
        __syncthreads();
    }
    if (t < SCAN_NB) g_bsum[t] = sh[t] - v0;   // exclusive
}
__global__ void k_scan3() {
    int i = blockIdx.x * blockDim.x + threadIdx.x;
    if (i < NN) {
        g_rowstart[i + 1] = g_tmp[i] + g_bsum[i >> 10];
        if (i == 0) g_rowstart[0] = 0;
        int c = g_cnt[i];
        g_dinv[i] = rsqrtf((float)c + 1.0f);
        g_cnt[i] = 0;
    }
}
__global__ void k_fill(const int* __restrict__ src, const int* __restrict__ dst) {
    int e = blockIdx.x * blockDim.x + threadIdx.x;
    if (e < NE) {
        int d = dst[e];
        int pos = g_rowstart[d] + atomicAdd(&g_cnt[d], 1);
        g_csrsrc[pos] = src[e];
    }
}

// ---------------- pack W1 [512,64] into mma b-fragments (hi/lo split) ----------------
__global__ void k_packB(const float* __restrict__ B) {
    int e = blockIdx.x * blockDim.x + threadIdx.x;
    if (e >= 8192) return;
    int l = e & 31, j = (e >> 5) & 7, s = e >> 8;
    int g = l >> 2, t = l & 3;
    int n = 8 * j + g;
    int k = 16 * s + 2 * t;
    float f0 = B[(size_t)k * 64 + n];
    float f1 = B[(size_t)(k + 1) * 64 + n];
    float f2 = B[(size_t)(k + 8) * 64 + n];
    float f3 = B[(size_t)(k + 9) * 64 + n];
    g_bfrag[e] = make_uint4(pkbf(f0, f1), pkbf(f2, f3),
                            pkbf(bfres(f0), bfres(f1)), pkbf(bfres(f2), bfres(f3)));
}
// ---------------- pack W2 [64,256] into mma b-fragments ----------------
__global__ void k_packB2(const float* __restrict__ B) {
    int e = blockIdx.x * blockDim.x + threadIdx.x;
    if (e >= 4096) return;
    int l = e & 31, j = (e >> 5) & 31, s = e >> 10;
    int g = l >> 2, t = l & 3;
    int n = 8 * j + g;
    int k = 16 * s + 2 * t;
    float f0 = B[(size_t)k * D2 + n];
    float f1 = B[(size_t)(k + 1) * D2 + n];
    float f2 = B[(size_t)(k + 8) * D2 + n];
    float f3 = B[(size_t)(k + 9) * D2 + n];
    g_bfrag2[e] = make_uint4(pkbf(f0, f1), pkbf(f2, f3),
                             pkbf(bfres(f0), bfres(f1)), pkbf(bfres(f2), bfres(f3)));
}

// ---------------- GEMM1 via mma.sync bf16 split-3: C[M,64] = A[M,512] @ W1 ----------------
#define G1A_STRIDE 36
#define G1_SMEM_BYTES (2 * 256 * 72 * 2)
__global__ __launch_bounds__(256) void k_gemm1_mma(const float* __restrict__ A,
                                                   float* __restrict__ C) {
    extern __shared__ char smem[];
    uint32_t* Ah = (uint32_t*)smem;
    uint32_t* Al = (uint32_t*)(smem + 256 * 72 * 2);
    int tid  = threadIdx.x;
    int lane = tid & 31;
    int w    = tid >> 5;
    int g    = lane >> 2;
    int t    = lane & 3;
    int bm   = blockIdx.x * 256;

    float acc[2][8][4];
#pragma unroll
    for (int m = 0; m < 2; m++)
#pragma unroll
        for (int j = 0; j < 8; j++)
#pragma unroll
            for (int q = 0; q < 4; q++) acc[m][j][q] = 0.f;

    int lr = tid >> 4;
    int c4 = (tid & 15) * 4;

    for (int ch = 0; ch < 8; ch++) {
        int k0 = ch * 64;
#pragma unroll
        for (int i = 0; i < 16; i++) {
            int row  = lr + 16 * i;
            int grow = bm + row;
            float4 v = (grow < NN) ? *(const float4*)(A + (size_t)grow * FIN + k0 + c4)
                                   : make_float4(0.f, 0.f, 0.f, 0.f);
            int idx = row * G1A_STRIDE + (c4 >> 1);
            *(uint2*)&Ah[idx] = make_uint2(pkbf(v.x, v.y), pkbf(v.z, v.w));
            *(uint2*)&Al[idx] = make_uint2(pkbf(bfres(v.x), bfres(v.y)), pkbf(bfres(v.z), bfres(v.w)));
        }
        __syncthreads();
#pragma unroll
        for (int s4 = 0; s4 < 4; s4++) {
            int kk = s4 * 16;
            int gs = ch * 4 + s4;
            uint32_t ah[2][4], al[2][4];
#pragma unroll
            for (int m = 0; m < 2; m++) {
                int r0 = w * 32 + m * 16 + g;
                int kc = (kk + 2 * t) >> 1;
                ah[m][0] = Ah[r0 * G1A_STRIDE + kc];
                ah[m][1] = Ah[(r0 + 8) * G1A_STRIDE + kc];
                ah[m][2] = Ah[r0 * G1A_STRIDE + kc + 4];
                ah[m][3] = Ah[(r0 + 8) * G1A_STRIDE + kc + 4];
                al[m][0] = Al[r0 * G1A_STRIDE + kc];
                al[m][1] = Al[(r0 + 8) * G1A_STRIDE + kc];
                al[m][2] = Al[r0 * G1A_STRIDE + kc + 4];
                al[m][3] = Al[(r0 + 8) * G1A_STRIDE + kc + 4];
            }
#pragma unroll
            for (int j = 0; j < 8; j++) {
                uint4 bf4 = __ldg(&g_bfrag[(gs * 8 + j) * 32 + lane]);
#pragma unroll
                for (int m = 0; m < 2; m++) {
                    mma_bf16(acc[m][j], ah[m], bf4.x, bf4.y);
                    mma_bf16(acc[m][j], ah[m], bf4.z, bf4.w);
                    mma_bf16(acc[m][j], al[m], bf4.x, bf4.y);
                }
            }
        }
        __syncthreads();
    }
#pragma unroll
    for (int m = 0; m < 2; m++) {
        int row = bm + w * 32 + m * 16 + g;
#pragma unroll
        for (int j = 0; j < 8; j++) {
            int col = 8 * j + 2 * t;
            if (row < NN)
                *(float2*)(C + (size_t)row * 64 + col) = make_float2(acc[m][j][0], acc[m][j][1]);
            if (row + 8 < NN)
                *(float2*)(C + (size_t)(row + 8) * 64 + col) = make_float2(acc[m][j][2], acc[m][j][3]);
        }
    }
}

// ---------------- GEMM2 via mma.sync bf16 split-3, fused W3 matvec (no C store) ----------------
// grid (ceil(NN/256), 4): each block does 256 rows x 64 cols (n-tiles bn..bn+7)
__global__ __launch_bounds__(256) void k_gemm2_mma(const float* __restrict__ A,
                                                   const float* __restrict__ bias,
                                                   const float* __restrict__ W3) {
    extern __shared__ char smem[];
    uint32_t* Ah = (uint32_t*)smem;                      // 256 x 36 (only 32 used)
    uint32_t* Al = (uint32_t*)(smem + 256 * 72 * 2);
    __shared__ float zpart[256];
    int tid  = threadIdx.x;
    int lane = tid & 31;
    int w    = tid >> 5;
    int g    = lane >> 2;
    int t    = lane & 3;
    int bm   = blockIdx.x * 256;
    int bn   = blockIdx.y * 64;
    zpart[tid] = 0.f;

    float acc[2][8][4];
#pragma unroll
    for (int m = 0; m < 2; m++)
#pragma unroll
        for (int j = 0; j < 8; j++)
#pragma unroll
            for (int q = 0; q < 4; q++) acc[m][j][q] = 0.f;

    // stage full A tile (K=64)
    int lr = tid >> 4;
    int c4 = (tid & 15) * 4;
#pragma unroll
    for (int i = 0; i < 16; i++) {
        int row  = lr + 16 * i;
        int grow = bm + row;
        float4 v = (grow < NN) ? *(const float4*)(A + (size_t)grow * D1 + c4)
                               : make_float4(0.f, 0.f, 0.f, 0.f);
        int idx = row * G1A_STRIDE + (c4 >> 1);
        *(uint2*)&Ah[idx] = make_uint2(pkbf(v.x, v.y), pkbf(v.z, v.w));
        *(uint2*)&Al[idx] = make_uint2(pkbf(bfres(v.x), bfres(v.y)), pkbf(bfres(v.z), bfres(v.w)));
    }
    __syncthreads();
#pragma unroll
    for (int s4 = 0; s4 < 4; s4++) {
        int kk = s4 * 16;
        uint32_t ah[2][4], al[2][4];
#pragma unroll
        for (int m = 0; m < 2; m++) {
            int r0 = w * 32 + m * 16 + g;
            int kc = (kk + 2 * t) >> 1;
            ah[m][0] = Ah[r0 * G1A_STRIDE + kc];
            ah[m][1] = Ah[(r0 + 8) * G1A_STRIDE + kc];
            ah[m][2] = Ah[r0 * G1A_STRIDE + kc + 4];
            ah[m][3] = Ah[(r0 + 8) * G1A_STRIDE + kc + 4];
            al[m][0] = Al[r0 * G1A_STRIDE + kc];
            al[m][1] = Al[(r0 + 8) * G1A_STRIDE + kc];
            al[m][2] = Al[r0 * G1A_STRIDE + kc + 4];
            al[m][3] = Al[(r0 + 8) * G1A_STRIDE + kc + 4];
        }
#pragma unroll
        for (int j = 0; j < 8; j++) {
            int ntile = blockIdx.y * 8 + j;
            uint4 bf4 = __ldg(&g_bfrag2[(s4 * 32 + ntile) * 32 + lane]);
#pragma unroll
            for (int m = 0; m < 2; m++) {
                mma_bf16(acc[m][j], ah[m], bf4.x, bf4.y);
                mma_bf16(acc[m][j], ah[m], bf4.z, bf4.w);
                mma_bf16(acc[m][j], al[m], bf4.x, bf4.y);
            }
        }
    }
    // epilogue: relu(acc + bias), dot with W3, reduce per row
#pragma unroll
    for (int m = 0; m < 2; m++) {
        int rl0 = w * 32 + m * 16 + g;
        float s0 = 0.f, s1 = 0.f;
#pragma unroll
        for (int j = 0; j < 8; j++) {
            int col = bn + 8 * j + 2 * t;
            float b0 = bias[col], b1 = bias[col + 1];
            float w0 = W3[col],  w1 = W3[col + 1];
            s0 += fmaxf(acc[m][j][0] + b0, 0.f) * w0 + fmaxf(acc[m][j][1] + b1, 0.f) * w1;
            s1 += fmaxf(acc[m][j][2] + b0, 0.f) * w0 + fmaxf(acc[m][j][3] + b1, 0.f) * w1;
        }
        atomicAdd(&zpart[rl0],     s0);
        atomicAdd(&zpart[rl0 + 8], s1);
    }
    __syncthreads();
    if (bm + tid < NN) atomicAdd(&g_z0[bm + tid], zpart[tid]);
}

// ---------------- CSR gather aggregation (64-dim), one warp per node ----------------
template <bool RELU>
__global__ __launch_bounds__(256) void k_gather64(const float* __restrict__ in,
                                                  float* __restrict__ out,
                                                  const float* __restrict__ bias) {
    int node = (blockIdx.x * blockDim.x + threadIdx.x) >> 5;
    if (node >= NN) return;
    int lane = threadIdx.x & 31;
    float dd = g_dinv[node];
    float2 self = ((const float2*)(in + (size_t)node * 64))[lane];
    float ax = self.x * dd, ay = self.y * dd;
    int e   = g_rowstart[node];
    int end = g_rowstart[node + 1];
    for (; e + 1 < end; e += 2) {
        int s0 = __ldg(&g_csrsrc[e]);
        int s1 = __ldg(&g_csrsrc[e + 1]);
        float w0 = __ldg(&g_dinv[s0]);
        float w1 = __ldg(&g_dinv[s1]);
        float2 v0 = ((const float2*)(in + (size_t)s0 * 64))[lane];
        float2 v1 = ((const float2*)(in + (size_t)s1 * 64))[lane];
        ax += v0.x * w0 + v1.x * w1;
        ay += v0.y * w0 + v1.y * w1;
    }
    if (e < end) {
        int s = __ldg(&g_csrsrc[e]);
        float w = __ldg(&g_dinv[s]);
        float2 v = ((const float2*)(in + (size_t)s * 64))[lane];
        ax += v.x * w;
        ay += v.y * w;
    }
    ax *= dd; ay *= dd;
    if (RELU) {
        float2 bb = ((const float2*)bias)[lane];
        ax = fmaxf(ax + bb.x, 0.f);
        ay = fmaxf(ay + bb.y, 0.f);
    }
    ((float2*)(out + (size_t)node * 64))[lane] = make_float2(ax, ay);
}

// ---------------- fused z aggregation + BCE loss ----------------
__global__ void k_zero(float* out) {
    if (blockIdx.x == 0 && threadIdx.x == 0) out[0] = 0.f;
}
__global__ __launch_bounds__(256) void k_zagg_loss(const float* __restrict__ b3,
                                                   const float* __restrict__ y,
                                                   float* __restrict__ out) {
    __shared__ float red[256];
    int i = blockIdx.x * blockDim.x + threadIdx.x;
    float v = 0.f;
    if (i < NN) {
        float dd  = g_dinv[i];
        float acc = g_z0[i] * dd;
        int e = g_rowstart[i], end = g_rowstart[i + 1];
        for (; e < end; e++) {
            int s = __ldg(&g_csrsrc[e]);
            acc += __ldg(&g_z0[s]) * __ldg(&g_dinv[s]);
        }
        float z = acc * dd + b3[0];
        float t = y[i];
        v = fmaxf(z, 0.f) - z * t + log1pf(expf(-fabsf(z)));
    }
    red[threadIdx.x] = v;
    __syncthreads();
    for (int s = 128; s > 0; s >>= 1) {
        if (threadIdx.x < s) red[threadIdx.x] += red[threadIdx.x + s];
        __syncthreads();
    }
    if (threadIdx.x == 0) atomicAdd(out, red[0] * (1.0f / NN));
}

// ---------------- launcher ----------------
extern "C" void kernel_launch(void* const* d_in, const int* in_sizes, int n_in,
                              void* d_out, int out_size) {
    const float* x  = (const float*)d_in[0];
    const int*   ei = (const int*)  d_in[1];
    const float* y  = (const float*)d_in[2];
    const float* W1 = (const float*)d_in[3];
    const float* b1 = (const float*)d_in[4];
    const float* W2 = (const float*)d_in[5];
    const float* b2 = (const float*)d_in[6];
    const float* W3 = (const float*)d_in[7];
    const float* b3 = (const float*)d_in[8];
    const int* src = ei;
    const int* dst = ei + NE;
    float* out = (float*)d_out;

    float *p_xw1, *p_h1, *p_ah1;
    cudaGetSymbolAddress((void**)&p_xw1, g_xw1);
    cudaGetSymbolAddress((void**)&p_h1,  g_h1);
    cudaGetSymbolAddress((void**)&p_ah1, g_ah1);

    cudaFuncSetAttribute(k_gemm1_mma, cudaFuncAttributeMaxDynamicSharedMemorySize, G1_SMEM_BYTES);
    cudaFuncSetAttribute(k_gemm2_mma, cudaFuncAttributeMaxDynamicSharedMemorySize, G1_SMEM_BYTES);

    const int T = 256;
    // ---- CSR build + dinv + weight fragment packs ----
    k_clear<<<(NN + T - 1) / T, T>>>();
    k_packB <<<32, 256>>>(W1);
    k_packB2<<<16, 256>>>(W2);
    k_hist <<<(NE + T - 1) / T, T>>>(dst);
    k_scan1<<<SCAN_NB, SCAN_B>>>();
    k_scan2<<<1, 128>>>();
    k_scan3<<<(NN + T - 1) / T, T>>>();
    k_fill <<<(NE + T - 1) / T, T>>>(src, dst);

    // ---- layer 1 ----
    k_gemm1_mma<<<(NN + 255) / 256, 256, G1_SMEM_BYTES>>>(x, p_xw1);
    k_gather64<true><<<(NN * 32 + T - 1) / T, T>>>(p_xw1, p_h1, b1);

    // ---- layer 2 + fused layer-3 matvec ----
    k_gather64<false><<<(NN * 32 + T - 1) / T, T>>>(p_h1, p_ah1, b1);
    dim3 g2((NN + 255) / 256, D2 / 64);
    k_gemm2_mma<<<g2, 256, G1_SMEM_BYTES>>>(p_ah1, b2, W3);

    // ---- z aggregation + loss ----
    k_zero<<<1, 32>>>(out);
    k_zagg_loss<<<(NN + T - 1) / T, T>>>(b3, y, out);
}

// round 8
// speedup vs baseline: 2.5339x; 1.1103x over previous
#include <cuda_runtime.h>
#include <cuda_bf16.h>
#include <stdint.h>
#include <math.h>

#define NN 100000
#define NE 1600000
#define FIN 512
#define D1 64
#define D2 256
#define SCAN_B 1024
#define SCAN_NB ((NN + SCAN_B - 1) / SCAN_B)

typedef unsigned long long ull;

__device__ float g_dinv[NN];
__device__ int   g_cnt[NN];
__device__ int   g_tmp[NN];
__device__ int   g_bsum[SCAN_NB];
__device__ int   g_rowstart[NN + 1];
__device__ int   g_csrsrc[NE];
__device__ uint4 g_bfrag[8192];            // packed W1 b-frags
__device__ uint4 g_bfrag2[4096];           // packed W2 b-frags
__device__ float g_xw1[(size_t)NN * D1];   // dinv-scaled x@W1
__device__ float g_h1 [(size_t)NN * D1];   // dinv-scaled relu(A xw1 + b1)
__device__ float g_ah1[(size_t)NN * D1];   // A h1 (unscaled)
__device__ float g_z0 [NN];

// ---------------- bf16 helpers ----------------
__device__ __forceinline__ uint32_t pkbf(float a, float b) {
    __nv_bfloat162 h = __floats2bfloat162_rn(a, b);
    return *(uint32_t*)&h;
}
__device__ __forceinline__ float bfres(float f) {
    return f - __bfloat162float(__float2bfloat16(f));
}
__device__ __forceinline__ void mma_bf16(float* c, const uint32_t* a, uint32_t b0, uint32_t b1) {
    asm("mma.sync.aligned.m16n8k16.row.col.f32.bf16.bf16.f32 "
        "{%0,%1,%2,%3}, {%4,%5,%6,%7}, {%8,%9}, {%0,%1,%2,%3};"
        : "+f"(c[0]), "+f"(c[1]), "+f"(c[2]), "+f"(c[3])
        : "r"(a[0]), "r"(a[1]), "r"(a[2]), "r"(a[3]), "r"(b0), "r"(b1));
}

// ---------------- CSR build ----------------
__global__ void k_clear() {
    int i = blockIdx.x * blockDim.x + threadIdx.x;
    if (i < NN) { g_cnt[i] = 0; g_z0[i] = 0.f; }
}
__global__ void k_hist(const int* __restrict__ dst) {
    int e = blockIdx.x * blockDim.x + threadIdx.x;
    if (e < NE) atomicAdd(&g_cnt[dst[e]], 1);
}
__global__ __launch_bounds__(SCAN_B) void k_scan1() {
    __shared__ int sh[SCAN_B];
    int t = threadIdx.x;
    int i = blockIdx.x * SCAN_B + t;
    sh[t] = (i < NN) ? g_cnt[i] : 0;
    __syncthreads();
#pragma unroll
    for (int off = 1; off < SCAN_B; off <<= 1) {
        int v = (t >= off) ? sh[t - off] : 0;
        __syncthreads();
        sh[t] += v;
        __syncthreads();
    }
    if (i < NN) g_tmp[i] = sh[t];
    if (t == SCAN_B - 1) g_bsum[blockIdx.x] = sh[t];
}
__global__ __launch_bounds__(128) void k_scan2() {
    __shared__ int sh[128];
    int t = threadIdx.x;
    int v0 = (t < SCAN_NB) ? g_bsum[t] : 0;
    sh[t] = v0;
    __syncthreads();
#pragma unroll
    for (int off = 1; off < 128; off <<= 1) {
        int v = (t >= off) ? sh[t - off] : 0;
        __syncthreads();
        sh[t] += v;
        __syncthreads();
    }
    if (t < SCAN_NB) g_bsum[t] = sh[t] - v0;
}
__global__ void k_scan3() {
    int i = blockIdx.x * blockDim.x + threadIdx.x;
    if (i < NN) {
        g_rowstart[i + 1] = g_tmp[i] + g_bsum[i >> 10];
        if (i == 0) g_rowstart[0] = 0;
        int c = g_cnt[i];
        g_dinv[i] = rsqrtf((float)c + 1.0f);
        g_cnt[i] = 0;
    }
}
__global__ void k_fill(const int* __restrict__ src, const int* __restrict__ dst) {
    int e = blockIdx.x * blockDim.x + threadIdx.x;
    if (e < NE) {
        int d = dst[e];
        int pos = g_rowstart[d] + atomicAdd(&g_cnt[d], 1);
        g_csrsrc[pos] = src[e];
    }
}

// ---------------- pack W1 [512,64] + W2 [64,256] into mma b-fragments ----------------
__global__ void k_packW(const float* __restrict__ B1, const float* __restrict__ B2) {
    int e = blockIdx.x * blockDim.x + threadIdx.x;
    if (e < 8192) {
        int l = e & 31, j = (e >> 5) & 7, s = e >> 8;
        int g = l >> 2, t = l & 3;
        int n = 8 * j + g;
        int k = 16 * s + 2 * t;
        float f0 = B1[(size_t)k * 64 + n];
        float f1 = B1[(size_t)(k + 1) * 64 + n];
        float f2 = B1[(size_t)(k + 8) * 64 + n];
        float f3 = B1[(size_t)(k + 9) * 64 + n];
        g_bfrag[e] = make_uint4(pkbf(f0, f1), pkbf(f2, f3),
                                pkbf(bfres(f0), bfres(f1)), pkbf(bfres(f2), bfres(f3)));
    } else if (e < 8192 + 4096) {
        int e2 = e - 8192;
        int l = e2 & 31, j = (e2 >> 5) & 31, s = e2 >> 10;
        int g = l >> 2, t = l & 3;
        int n = 8 * j + g;
        int k = 16 * s + 2 * t;
        float f0 = B2[(size_t)k * D2 + n];
        float f1 = B2[(size_t)(k + 1) * D2 + n];
        float f2 = B2[(size_t)(k + 8) * D2 + n];
        float f3 = B2[(size_t)(k + 9) * D2 + n];
        g_bfrag2[e2] = make_uint4(pkbf(f0, f1), pkbf(f2, f3),
                                  pkbf(bfres(f0), bfres(f1)), pkbf(bfres(f2), bfres(f3)));
    }
}

// ---------------- GEMM1 via mma.sync bf16 split-3; epilogue scales rows by dinv ----------------
#define G1A_STRIDE 36
#define G1_SMEM_BYTES (2 * 256 * 72 * 2)
__global__ __launch_bounds__(256) void k_gemm1_mma(const float* __restrict__ A,
                                                   float* __restrict__ C) {
    extern __shared__ char smem[];
    uint32_t* Ah = (uint32_t*)smem;
    uint32_t* Al = (uint32_t*)(smem + 256 * 72 * 2);
    int tid  = threadIdx.x;
    int lane = tid & 31;
    int w    = tid >> 5;
    int g    = lane >> 2;
    int t    = lane & 3;
    int bm   = blockIdx.x * 256;

    float acc[2][8][4];
#pragma unroll
    for (int m = 0; m < 2; m++)
#pragma unroll
        for (int j = 0; j < 8; j++)
#pragma unroll
            for (int q = 0; q < 4; q++) acc[m][j][q] = 0.f;

    int lr = tid >> 4;
    int c4 = (tid & 15) * 4;

    for (int ch = 0; ch < 8; ch++) {
        int k0 = ch * 64;
#pragma unroll
        for (int i = 0; i < 16; i++) {
            int row  = lr + 16 * i;
            int grow = bm + row;
            float4 v = (grow < NN) ? *(const float4*)(A + (size_t)grow * FIN + k0 + c4)
                                   : make_float4(0.f, 0.f, 0.f, 0.f);
            int idx = row * G1A_STRIDE + (c4 >> 1);
            *(uint2*)&Ah[idx] = make_uint2(pkbf(v.x, v.y), pkbf(v.z, v.w));
            *(uint2*)&Al[idx] = make_uint2(pkbf(bfres(v.x), bfres(v.y)), pkbf(bfres(v.z), bfres(v.w)));
        }
        __syncthreads();
#pragma unroll
        for (int s4 = 0; s4 < 4; s4++) {
            int kk = s4 * 16;
            int gs = ch * 4 + s4;
            uint32_t ah[2][4], al[2][4];
#pragma unroll
            for (int m = 0; m < 2; m++) {
                int r0 = w * 32 + m * 16 + g;
                int kc = (kk + 2 * t) >> 1;
                ah[m][0] = Ah[r0 * G1A_STRIDE + kc];
                ah[m][1] = Ah[(r0 + 8) * G1A_STRIDE + kc];
                ah[m][2] = Ah[r0 * G1A_STRIDE + kc + 4];
                ah[m][3] = Ah[(r0 + 8) * G1A_STRIDE + kc + 4];
                al[m][0] = Al[r0 * G1A_STRIDE + kc];
                al[m][1] = Al[(r0 + 8) * G1A_STRIDE + kc];
                al[m][2] = Al[r0 * G1A_STRIDE + kc + 4];
                al[m][3] = Al[(r0 + 8) * G1A_STRIDE + kc + 4];
            }
#pragma unroll
            for (int j = 0; j < 8; j++) {
                uint4 bf4 = __ldg(&g_bfrag[(gs * 8 + j) * 32 + lane]);
#pragma unroll
                for (int m = 0; m < 2; m++) {
                    mma_bf16(acc[m][j], ah[m], bf4.x, bf4.y);
                    mma_bf16(acc[m][j], ah[m], bf4.z, bf4.w);
                    mma_bf16(acc[m][j], al[m], bf4.x, bf4.y);
                }
            }
        }
        __syncthreads();
    }
#pragma unroll
    for (int m = 0; m < 2; m++) {
        int row = bm + w * 32 + m * 16 + g;
        float d0 = (row < NN)     ? g_dinv[row]     : 0.f;
        float d1 = (row + 8 < NN) ? g_dinv[row + 8] : 0.f;
#pragma unroll
        for (int j = 0; j < 8; j++) {
            int col = 8 * j + 2 * t;
            if (row < NN)
                *(float2*)(C + (size_t)row * 64 + col) = make_float2(acc[m][j][0] * d0, acc[m][j][1] * d0);
            if (row + 8 < NN)
                *(float2*)(C + (size_t)(row + 8) * 64 + col) = make_float2(acc[m][j][2] * d1, acc[m][j][3] * d1);
        }
    }
}

// ---------------- GEMM2 via mma.sync bf16 split-3, fused W3 matvec ----------------
__global__ __launch_bounds__(256) void k_gemm2_mma(const float* __restrict__ A,
                                                   const float* __restrict__ bias,
                                                   const float* __restrict__ W3) {
    extern __shared__ char smem[];
    uint32_t* Ah = (uint32_t*)smem;
    uint32_t* Al = (uint32_t*)(smem + 256 * 72 * 2);
    __shared__ float zpart[256];
    int tid  = threadIdx.x;
    int lane = tid & 31;
    int w    = tid >> 5;
    int g    = lane >> 2;
    int t    = lane & 3;
    int bm   = blockIdx.x * 256;
    int bn   = blockIdx.y * 64;
    zpart[tid] = 0.f;

    float acc[2][8][4];
#pragma unroll
    for (int m = 0; m < 2; m++)
#pragma unroll
        for (int j = 0; j < 8; j++)
#pragma unroll
            for (int q = 0; q < 4; q++) acc[m][j][q] = 0.f;

    int lr = tid >> 4;
    int c4 = (tid & 15) * 4;
#pragma unroll
    for (int i = 0; i < 16; i++) {
        int row  = lr + 16 * i;
        int grow = bm + row;
        float4 v = (grow < NN) ? *(const float4*)(A + (size_t)grow * D1 + c4)
                               : make_float4(0.f, 0.f, 0.f, 0.f);
        int idx = row * G1A_STRIDE + (c4 >> 1);
        *(uint2*)&Ah[idx] = make_uint2(pkbf(v.x, v.y), pkbf(v.z, v.w));
        *(uint2*)&Al[idx] = make_uint2(pkbf(bfres(v.x), bfres(v.y)), pkbf(bfres(v.z), bfres(v.w)));
    }
    __syncthreads();
#pragma unroll
    for (int s4 = 0; s4 < 4; s4++) {
        int kk = s4 * 16;
        uint32_t ah[2][4], al[2][4];
#pragma unroll
        for (int m = 0; m < 2; m++) {
            int r0 = w * 32 + m * 16 + g;
            int kc = (kk + 2 * t) >> 1;
            ah[m][0] = Ah[r0 * G1A_STRIDE + kc];
            ah[m][1] = Ah[(r0 + 8) * G1A_STRIDE + kc];
            ah[m][2] = Ah[r0 * G1A_STRIDE + kc + 4];
            ah[m][3] = Ah[(r0 + 8) * G1A_STRIDE + kc + 4];
            al[m][0] = Al[r0 * G1A_STRIDE + kc];
            al[m][1] = Al[(r0 + 8) * G1A_STRIDE + kc];
            al[m][2] = Al[r0 * G1A_STRIDE + kc + 4];
            al[m][3] = Al[(r0 + 8) * G1A_STRIDE + kc + 4];
        }
#pragma unroll
        for (int j = 0; j < 8; j++) {
            int ntile = blockIdx.y * 8 + j;
            uint4 bf4 = __ldg(&g_bfrag2[(s4 * 32 + ntile) * 32 + lane]);
#pragma unroll
            for (int m = 0; m < 2; m++) {
                mma_bf16(acc[m][j], ah[m], bf4.x, bf4.y);
                mma_bf16(acc[m][j], ah[m], bf4.z, bf4.w);
                mma_bf16(acc[m][j], al[m], bf4.x, bf4.y);
            }
        }
    }
#pragma unroll
    for (int m = 0; m < 2; m++) {
        int rl0 = w * 32 + m * 16 + g;
        float s0 = 0.f, s1 = 0.f;
#pragma unroll
        for (int j = 0; j < 8; j++) {
            int col = bn + 8 * j + 2 * t;
            float b0 = bias[col], b1 = bias[col + 1];
            float w0 = W3[col],  w1 = W3[col + 1];
            s0 += fmaxf(acc[m][j][0] + b0, 0.f) * w0 + fmaxf(acc[m][j][1] + b1, 0.f) * w1;
            s1 += fmaxf(acc[m][j][2] + b0, 0.f) * w0 + fmaxf(acc[m][j][3] + b1, 0.f) * w1;
        }
        atomicAdd(&zpart[rl0],     s0);
        atomicAdd(&zpart[rl0 + 8], s1);
    }
    __syncthreads();
    if (bm + tid < NN) atomicAdd(&g_z0[bm + tid], zpart[tid]);
}

// ---------------- CSR gather (input pre-scaled by dinv), one warp per node, unroll-4 ----
// out[d] = f( dd * (Σ_s in[s] + in[d]) ), RELU path: relu(+bias) then scale by dd again
template <bool RELU_SCALE>
__global__ __launch_bounds__(256) void k_gather64(const float* __restrict__ in,
                                                  float* __restrict__ out,
                                                  const float* __restrict__ bias) {
    int node = (blockIdx.x * blockDim.x + threadIdx.x) >> 5;
    if (node >= NN) return;
    int lane = threadIdx.x & 31;
    const float2* base = (const float2*)in;
    float dd = g_dinv[node];
    float2 self = base[node * 32 + lane];
    float ax = self.x, ay = self.y;
    int e   = g_rowstart[node];
    int end = g_rowstart[node + 1];
    for (; e + 3 < end; e += 4) {
        int s0 = __ldg(&g_csrsrc[e]);
        int s1 = __ldg(&g_csrsrc[e + 1]);
        int s2 = __ldg(&g_csrsrc[e + 2]);
        int s3 = __ldg(&g_csrsrc[e + 3]);
        float2 v0 = base[s0 * 32 + lane];
        float2 v1 = base[s1 * 32 + lane];
        float2 v2 = base[s2 * 32 + lane];
        float2 v3 = base[s3 * 32 + lane];
        ax += (v0.x + v1.x) + (v2.x + v3.x);
        ay += (v0.y + v1.y) + (v2.y + v3.y);
    }
    for (; e < end; e++) {
        int s = __ldg(&g_csrsrc[e]);
        float2 v = base[s * 32 + lane];
        ax += v.x;
        ay += v.y;
    }
    ax *= dd; ay *= dd;
    if (RELU_SCALE) {
        float2 bb = ((const float2*)bias)[lane];
        ax = fmaxf(ax + bb.x, 0.f) * dd;       // output pre-scaled for next gather
        ay = fmaxf(ay + bb.y, 0.f) * dd;
    }
    ((float2*)(out + (size_t)node * 64))[lane] = make_float2(ax, ay);
}

// ---------------- scale z0 by dinv (in place) ----------------
__global__ void k_scalez() {
    int i = blockIdx.x * blockDim.x + threadIdx.x;
    if (i < NN) g_z0[i] *= g_dinv[i];
}

// ---------------- fused z aggregation + BCE loss (z0 pre-scaled) ----------------
__global__ void k_zero(float* out) {
    if (blockIdx.x == 0 && threadIdx.x == 0) out[0] = 0.f;
}
__global__ __launch_bounds__(256) void k_zagg_loss(const float* __restrict__ b3,
                                                   const float* __restrict__ y,
                                                   float* __restrict__ out) {
    __shared__ float red[256];
    int i = blockIdx.x * blockDim.x + threadIdx.x;
    float v = 0.f;
    if (i < NN) {
        float dd  = g_dinv[i];
        float acc = g_z0[i];
        int e = g_rowstart[i], end = g_rowstart[i + 1];
        for (; e + 3 < end; e += 4) {
            int s0 = __ldg(&g_csrsrc[e]);
            int s1 = __ldg(&g_csrsrc[e + 1]);
            int s2 = __ldg(&g_csrsrc[e + 2]);
            int s3 = __ldg(&g_csrsrc[e + 3]);
            acc += (__ldg(&g_z0[s0]) + __ldg(&g_z0[s1])) + (__ldg(&g_z0[s2]) + __ldg(&g_z0[s3]));
        }
        for (; e < end; e++) acc += __ldg(&g_z0[__ldg(&g_csrsrc[e])]);
        float z = acc * dd + b3[0];
        float t = y[i];
        v = fmaxf(z, 0.f) - z * t + log1pf(expf(-fabsf(z)));
    }
    red[threadIdx.x] = v;
    __syncthreads();
    for (int s = 128; s > 0; s >>= 1) {
        if (threadIdx.x < s) red[threadIdx.x] += red[threadIdx.x + s];
        __syncthreads();
    }
    if (threadIdx.x == 0) atomicAdd(out, red[0] * (1.0f / NN));
}

// ---------------- launcher ----------------
extern "C" void kernel_launch(void* const* d_in, const int* in_sizes, int n_in,
                              void* d_out, int out_size) {
    const float* x  = (const float*)d_in[0];
    const int*   ei = (const int*)  d_in[1];
    const float* y  = (const float*)d_in[2];
    const float* W1 = (const float*)d_in[3];
    const float* b1 = (const float*)d_in[4];
    const float* W2 = (const float*)d_in[5];
    const float* b2 = (const float*)d_in[6];
    const float* W3 = (const float*)d_in[7];
    const float* b3 = (const float*)d_in[8];
    const int* src = ei;
    const int* dst = ei + NE;
    float* out = (float*)d_out;

    float *p_xw1, *p_h1, *p_ah1;
    cudaGetSymbolAddress((void**)&p_xw1, g_xw1);
    cudaGetSymbolAddress((void**)&p_h1,  g_h1);
    cudaGetSymbolAddress((void**)&p_ah1, g_ah1);

    cudaFuncSetAttribute(k_gemm1_mma, cudaFuncAttributeMaxDynamicSharedMemorySize, G1_SMEM_BYTES);
    cudaFuncSetAttribute(k_gemm2_mma, cudaFuncAttributeMaxDynamicSharedMemorySize, G1_SMEM_BYTES);

    const int T = 256;
    // ---- CSR build + dinv + weight packs ----
    k_clear<<<(NN + T - 1) / T, T>>>();
    k_packW<<<48, 256>>>(W1, W2);
    k_hist <<<(NE + T - 1) / T, T>>>(dst);
    k_scan1<<<SCAN_NB, SCAN_B>>>();
    k_scan2<<<1, 128>>>();
    k_scan3<<<(NN + T - 1) / T, T>>>();
    k_fill <<<(NE + T - 1) / T, T>>>(src, dst);

    // ---- layer 1 (xw1 stored dinv-scaled) ----
    k_gemm1_mma<<<(NN + 255) / 256, 256, G1_SMEM_BYTES>>>(x, p_xw1);
    k_gather64<true><<<(NN * 32 + T - 1) / T, T>>>(p_xw1, p_h1, b1);   // h1 stored dinv-scaled

    // ---- layer 2 + fused layer-3 matvec ----
    k_gather64<false><<<(NN * 32 + T - 1) / T, T>>>(p_h1, p_ah1, b1);  // ah1 unscaled
    dim3 g2((NN + 255) / 256, D2 / 64);
    k_gemm2_mma<<<g2, 256, G1_SMEM_BYTES>>>(p_ah1, b2, W3);

    // ---- z aggregation + loss ----
    k_scalez<<<(NN + T - 1) / T, T>>>();
    k_zero<<<1, 32>>>(out);
    k_zagg_loss<<<(NN + T - 1) / T, T>>>(b3, y, out);
}

// round 9
// speedup vs baseline: 2.5942x; 1.0238x over previous
#include <cuda_runtime.h>
#include <cuda_bf16.h>
#include <stdint.h>
#include <math.h>

#define NN 100000
#define NE 1600000
#define FIN 512
#define D1 64
#define D2 256
#define SCAN_B 1024
#define SCAN_NB ((NN + SCAN_B - 1) / SCAN_B)

__device__ float    g_dinv[NN];
__device__ int      g_cnt[NN];
__device__ int      g_tmp[NN];
__device__ int      g_bsum[SCAN_NB];
__device__ int      g_rowstart[NN + 1];
__device__ int      g_csrsrc[NE];
__device__ uint4    g_bfrag[8192];             // packed W1 b-frags
__device__ uint4    g_bfrag2[4096];            // packed W2 b-frags
__device__ uint32_t g_xw1[(size_t)NN * 32];    // bf16x2, dinv-scaled x@W1
__device__ uint32_t g_h1 [(size_t)NN * 32];    // bf16x2, dinv-scaled relu(A xw1 + b1)
__device__ float    g_ah1[(size_t)NN * D1];    // A h1 (fp32)
__device__ float    g_z0 [NN];                 // dinv-scaled h2@W3

// ---------------- bf16 helpers ----------------
__device__ __forceinline__ uint32_t pkbf(float a, float b) {
    __nv_bfloat162 h = __floats2bfloat162_rn(a, b);
    return *(uint32_t*)&h;
}
__device__ __forceinline__ float2 upbf(uint32_t v) {
    __nv_bfloat162 h = *(__nv_bfloat162*)&v;
    return __bfloat1622float2(h);
}
__device__ __forceinline__ float bfres(float f) {
    return f - __bfloat162float(__float2bfloat16(f));
}
__device__ __forceinline__ void mma_bf16(float* c, const uint32_t* a, uint32_t b0, uint32_t b1) {
    asm("mma.sync.aligned.m16n8k16.row.col.f32.bf16.bf16.f32 "
        "{%0,%1,%2,%3}, {%4,%5,%6,%7}, {%8,%9}, {%0,%1,%2,%3};"
        : "+f"(c[0]), "+f"(c[1]), "+f"(c[2]), "+f"(c[3])
        : "r"(a[0]), "r"(a[1]), "r"(a[2]), "r"(a[3]), "r"(b0), "r"(b1));
}

// ---------------- CSR build ----------------
__global__ void k_clear() {
    int i = blockIdx.x * blockDim.x + threadIdx.x;
    if (i < NN) g_cnt[i] = 0;
}
__global__ void k_hist(const int* __restrict__ dst) {
    int e = blockIdx.x * blockDim.x + threadIdx.x;
    if (e < NE) atomicAdd(&g_cnt[dst[e]], 1);
}
__global__ __launch_bounds__(SCAN_B) void k_scan1() {
    __shared__ int sh[SCAN_B];
    int t = threadIdx.x;
    int i = blockIdx.x * SCAN_B + t;
    sh[t] = (i < NN) ? g_cnt[i] : 0;
    __syncthreads();
#pragma unroll
    for (int off = 1; off < SCAN_B; off <<= 1) {
        int v = (t >= off) ? sh[t - off] : 0;
        __syncthreads();
        sh[t] += v;
        __syncthreads();
    }
    if (i < NN) g_tmp[i] = sh[t];
    if (t == SCAN_B - 1) g_bsum[blockIdx.x] = sh[t];
}
__global__ __launch_bounds__(128) void k_scan2() {
    __shared__ int sh[128];
    int t = threadIdx.x;
    int v0 = (t < SCAN_NB) ? g_bsum[t] : 0;
    sh[t] = v0;
    __syncthreads();
#pragma unroll
    for (int off = 1; off < 128; off <<= 1) {
        int v = (t >= off) ? sh[t - off] : 0;
        __syncthreads();
        sh[t] += v;
        __syncthreads();
    }
    if (t < SCAN_NB) g_bsum[t] = sh[t] - v0;
}
__global__ void k_scan3() {
    int i = blockIdx.x * blockDim.x + threadIdx.x;
    if (i < NN) {
        g_rowstart[i + 1] = g_tmp[i] + g_bsum[i >> 10];
        if (i == 0) g_rowstart[0] = 0;
        int c = g_cnt[i];
        g_dinv[i] = rsqrtf((float)c + 1.0f);
        g_cnt[i] = 0;
    }
}
__global__ void k_fill(const int* __restrict__ src, const int* __restrict__ dst) {
    int e = blockIdx.x * blockDim.x + threadIdx.x;
    if (e < NE) {
        int d = dst[e];
        int pos = g_rowstart[d] + atomicAdd(&g_cnt[d], 1);
        g_csrsrc[pos] = src[e];
    }
}

// ---------------- pack W1 [512,64] + W2 [64,256] into mma b-fragments ----------------
__global__ void k_packW(const float* __restrict__ B1, const float* __restrict__ B2) {
    int e = blockIdx.x * blockDim.x + threadIdx.x;
    if (e < 8192) {
        int l = e & 31, j = (e >> 5) & 7, s = e >> 8;
        int g = l >> 2, t = l & 3;
        int n = 8 * j + g;
        int k = 16 * s + 2 * t;
        float f0 = B1[(size_t)k * 64 + n];
        float f1 = B1[(size_t)(k + 1) * 64 + n];
        float f2 = B1[(size_t)(k + 8) * 64 + n];
        float f3 = B1[(size_t)(k + 9) * 64 + n];
        g_bfrag[e] = make_uint4(pkbf(f0, f1), pkbf(f2, f3),
                                pkbf(bfres(f0), bfres(f1)), pkbf(bfres(f2), bfres(f3)));
    } else if (e < 8192 + 4096) {
        int e2 = e - 8192;
        int l = e2 & 31, j = (e2 >> 5) & 31, s = e2 >> 10;
        int g = l >> 2, t = l & 3;
        int n = 8 * j + g;
        int k = 16 * s + 2 * t;
        float f0 = B2[(size_t)k * D2 + n];
        float f1 = B2[(size_t)(k + 1) * D2 + n];
        float f2 = B2[(size_t)(k + 8) * D2 + n];
        float f3 = B2[(size_t)(k + 9) * D2 + n];
        g_bfrag2[e2] = make_uint4(pkbf(f0, f1), pkbf(f2, f3),
                                  pkbf(bfres(f0), bfres(f1)), pkbf(bfres(f2), bfres(f3)));
    }
}

// ---------------- GEMM1 via mma.sync bf16 split-3; writes dinv-scaled bf16x2 ----------------
#define G1A_STRIDE 36
#define G1_SMEM_BYTES (2 * 256 * 72 * 2)
__global__ __launch_bounds__(256) void k_gemm1_mma(const float* __restrict__ A,
                                                   uint32_t* __restrict__ C) {
    extern __shared__ char smem[];
    uint32_t* Ah = (uint32_t*)smem;
    uint32_t* Al = (uint32_t*)(smem + 256 * 72 * 2);
    int tid  = threadIdx.x;
    int lane = tid & 31;
    int w    = tid >> 5;
    int g    = lane >> 2;
    int t    = lane & 3;
    int bm   = blockIdx.x * 256;

    float acc[2][8][4];
#pragma unroll
    for (int m = 0; m < 2; m++)
#pragma unroll
        for (int j = 0; j < 8; j++)
#pragma unroll
            for (int q = 0; q < 4; q++) acc[m][j][q] = 0.f;

    int lr = tid >> 4;
    int c4 = (tid & 15) * 4;

    for (int ch = 0; ch < 8; ch++) {
        int k0 = ch * 64;
#pragma unroll
        for (int i = 0; i < 16; i++) {
            int row  = lr + 16 * i;
            int grow = bm + row;
            float4 v = (grow < NN) ? *(const float4*)(A + (size_t)grow * FIN + k0 + c4)
                                   : make_float4(0.f, 0.f, 0.f, 0.f);
            int idx = row * G1A_STRIDE + (c4 >> 1);
            *(uint2*)&Ah[idx] = make_uint2(pkbf(v.x, v.y), pkbf(v.z, v.w));
            *(uint2*)&Al[idx] = make_uint2(pkbf(bfres(v.x), bfres(v.y)), pkbf(bfres(v.z), bfres(v.w)));
        }
        __syncthreads();
#pragma unroll
        for (int s4 = 0; s4 < 4; s4++) {
            int kk = s4 * 16;
            int gs = ch * 4 + s4;
            uint32_t ah[2][4], al[2][4];
#pragma unroll
            for (int m = 0; m < 2; m++) {
                int r0 = w * 32 + m * 16 + g;
                int kc = (kk + 2 * t) >> 1;
                ah[m][0] = Ah[r0 * G1A_STRIDE + kc];
                ah[m][1] = Ah[(r0 + 8) * G1A_STRIDE + kc];
                ah[m][2] = Ah[r0 * G1A_STRIDE + kc + 4];
                ah[m][3] = Ah[(r0 + 8) * G1A_STRIDE + kc + 4];
                al[m][0] = Al[r0 * G1A_STRIDE + kc];
                al[m][1] = Al[(r0 + 8) * G1A_STRIDE + kc];
                al[m][2] = Al[r0 * G1A_STRIDE + kc + 4];
                al[m][3] = Al[(r0 + 8) * G1A_STRIDE + kc + 4];
            }
#pragma unroll
            for (int j = 0; j < 8; j++) {
                uint4 bf4 = __ldg(&g_bfrag[(gs * 8 + j) * 32 + lane]);
#pragma unroll
                for (int m = 0; m < 2; m++) {
                    mma_bf16(acc[m][j], ah[m], bf4.x, bf4.y);
                    mma_bf16(acc[m][j], ah[m], bf4.z, bf4.w);
                    mma_bf16(acc[m][j], al[m], bf4.x, bf4.y);
                }
            }
        }
        __syncthreads();
    }
#pragma unroll
    for (int m = 0; m < 2; m++) {
        int row = bm + w * 32 + m * 16 + g;
        float d0 = (row < NN)     ? g_dinv[row]     : 0.f;
        float d1 = (row + 8 < NN) ? g_dinv[row + 8] : 0.f;
#pragma unroll
        for (int j = 0; j < 8; j++) {
            int cp = 4 * j + t;   // bf16x2 index for cols 8j+2t, 8j+2t+1
            if (row < NN)
                C[(size_t)row * 32 + cp] = pkbf(acc[m][j][0] * d0, acc[m][j][1] * d0);
            if (row + 8 < NN)
                C[(size_t)(row + 8) * 32 + cp] = pkbf(acc[m][j][2] * d1, acc[m][j][3] * d1);
        }
    }
}

// ---------------- gather 1: bf16 in -> bf16 out (relu+bias, dinv^2 scaling) ----------------
__global__ __launch_bounds__(256) void k_gather_bf2bf(const uint32_t* __restrict__ in,
                                                      uint32_t* __restrict__ out,
                                                      const float* __restrict__ bias) {
    int node = (blockIdx.x * blockDim.x + threadIdx.x) >> 5;
    if (node >= NN) return;
    int lane = threadIdx.x & 31;
    float dd = g_dinv[node];
    float2 self = upbf(in[node * 32 + lane]);
    float ax = self.x, ay = self.y;
    int e   = g_rowstart[node];
    int end = g_rowstart[node + 1];
    for (; e + 3 < end; e += 4) {
        int s0 = __ldg(&g_csrsrc[e]);
        int s1 = __ldg(&g_csrsrc[e + 1]);
        int s2 = __ldg(&g_csrsrc[e + 2]);
        int s3 = __ldg(&g_csrsrc[e + 3]);
        float2 v0 = upbf(__ldg(&in[s0 * 32 + lane]));
        float2 v1 = upbf(__ldg(&in[s1 * 32 + lane]));
        float2 v2 = upbf(__ldg(&in[s2 * 32 + lane]));
        float2 v3 = upbf(__ldg(&in[s3 * 32 + lane]));
        ax += (v0.x + v1.x) + (v2.x + v3.x);
        ay += (v0.y + v1.y) + (v2.y + v3.y);
    }
    for (; e < end; e++) {
        float2 v = upbf(__ldg(&in[__ldg(&g_csrsrc[e]) * 32 + lane]));
        ax += v.x;
        ay += v.y;
    }
    float2 bb = ((const float2*)bias)[lane];
    ax = fmaxf(ax * dd + bb.x, 0.f) * dd;   // output pre-scaled for next gather
    ay = fmaxf(ay * dd + bb.y, 0.f) * dd;
    out[node * 32 + lane] = pkbf(ax, ay);
}

// ---------------- gather 2: bf16 in -> fp32 out (plain aggregate, dinv scale) ----------------
__global__ __launch_bounds__(256) void k_gather_bf2f(const uint32_t* __restrict__ in,
                                                     float* __restrict__ out) {
    int node = (blockIdx.x * blockDim.x + threadIdx.x) >> 5;
    if (node >= NN) return;
    int lane = threadIdx.x & 31;
    float dd = g_dinv[node];
    float2 self = upbf(in[node * 32 + lane]);
    float ax = self.x, ay = self.y;
    int e   = g_rowstart[node];
    int end = g_rowstart[node + 1];
    for (; e + 3 < end; e += 4) {
        int s0 = __ldg(&g_csrsrc[e]);
        int s1 = __ldg(&g_csrsrc[e + 1]);
        int s2 = __ldg(&g_csrsrc[e + 2]);
        int s3 = __ldg(&g_csrsrc[e + 3]);
        float2 v0 = upbf(__ldg(&in[s0 * 32 + lane]));
        float2 v1 = upbf(__ldg(&in[s1 * 32 + lane]));
        float2 v2 = upbf(__ldg(&in[s2 * 32 + lane]));
        float2 v3 = upbf(__ldg(&in[s3 * 32 + lane]));
        ax += (v0.x + v1.x) + (v2.x + v3.x);
        ay += (v0.y + v1.y) + (v2.y + v3.y);
    }
    for (; e < end; e++) {
        float2 v = upbf(__ldg(&in[__ldg(&g_csrsrc[e]) * 32 + lane]));
        ax += v.x;
        ay += v.y;
    }
    ((float2*)(out + (size_t)node * 64))[lane] = make_float2(ax * dd, ay * dd);
}

// ---------------- GEMM2: one block per 256 rows, loops all 4 n-chunks; writes scaled z0 ----
__global__ __launch_bounds__(256) void k_gemm2_mma(const float* __restrict__ A,
                                                   const float* __restrict__ bias,
                                                   const float* __restrict__ W3) {
    extern __shared__ char smem[];
    uint32_t* Ah = (uint32_t*)smem;
    uint32_t* Al = (uint32_t*)(smem + 256 * 72 * 2);
    __shared__ float zpart[256];
    int tid  = threadIdx.x;
    int lane = tid & 31;
    int w    = tid >> 5;
    int g    = lane >> 2;
    int t    = lane & 3;
    int bm   = blockIdx.x * 256;
    zpart[tid] = 0.f;

    int lr = tid >> 4;
    int c4 = (tid & 15) * 4;
#pragma unroll
    for (int i = 0; i < 16; i++) {
        int row  = lr + 16 * i;
        int grow = bm + row;
        float4 v = (grow < NN) ? *(const float4*)(A + (size_t)grow * D1 + c4)
                               : make_float4(0.f, 0.f, 0.f, 0.f);
        int idx = row * G1A_STRIDE + (c4 >> 1);
        *(uint2*)&Ah[idx] = make_uint2(pkbf(v.x, v.y), pkbf(v.z, v.w));
        *(uint2*)&Al[idx] = make_uint2(pkbf(bfres(v.x), bfres(v.y)), pkbf(bfres(v.z), bfres(v.w)));
    }
    __syncthreads();

    for (int c = 0; c < 4; c++) {            // n-chunk: cols c*64 .. c*64+63
        float acc[2][8][4];
#pragma unroll
        for (int m = 0; m < 2; m++)
#pragma unroll
            for (int j = 0; j < 8; j++)
#pragma unroll
                for (int q = 0; q < 4; q++) acc[m][j][q] = 0.f;
#pragma unroll
        for (int s4 = 0; s4 < 4; s4++) {
            int kk = s4 * 16;
            uint32_t ah[2][4], al[2][4];
#pragma unroll
            for (int m = 0; m < 2; m++) {
                int r0 = w * 32 + m * 16 + g;
                int kc = (kk + 2 * t) >> 1;
                ah[m][0] = Ah[r0 * G1A_STRIDE + kc];
                ah[m][1] = Ah[(r0 + 8) * G1A_STRIDE + kc];
                ah[m][2] = Ah[r0 * G1A_STRIDE + kc + 4];
                ah[m][3] = Ah[(r0 + 8) * G1A_STRIDE + kc + 4];
                al[m][0] = Al[r0 * G1A_STRIDE + kc];
                al[m][1] = Al[(r0 + 8) * G1A_STRIDE + kc];
                al[m][2] = Al[r0 * G1A_STRIDE + kc + 4];
                al[m][3] = Al[(r0 + 8) * G1A_STRIDE + kc + 4];
            }
#pragma unroll
            for (int j = 0; j < 8; j++) {
                uint4 bf4 = __ldg(&g_bfrag2[(s4 * 32 + c * 8 + j) * 32 + lane]);
#pragma unroll
                for (int m = 0; m < 2; m++) {
                    mma_bf16(acc[m][j], ah[m], bf4.x, bf4.y);
                    mma_bf16(acc[m][j], ah[m], bf4.z, bf4.w);
                    mma_bf16(acc[m][j], al[m], bf4.x, bf4.y);
                }
            }
        }
#pragma unroll
        for (int m = 0; m < 2; m++) {
            int rl0 = w * 32 + m * 16 + g;
            float s0 = 0.f, s1 = 0.f;
#pragma unroll
            for (int j = 0; j < 8; j++) {
                int col = c * 64 + 8 * j + 2 * t;
                float b0 = bias[col], b1 = bias[col + 1];
                float w0 = W3[col],  w1 = W3[col + 1];
                s0 += fmaxf(acc[m][j][0] + b0, 0.f) * w0 + fmaxf(acc[m][j][1] + b1, 0.f) * w1;
                s1 += fmaxf(acc[m][j][2] + b0, 0.f) * w0 + fmaxf(acc[m][j][3] + b1, 0.f) * w1;
            }
            atomicAdd(&zpart[rl0],     s0);
            atomicAdd(&zpart[rl0 + 8], s1);
        }
    }
    __syncthreads();
    int row = bm + tid;
    if (row < NN) g_z0[row] = zpart[tid] * g_dinv[row];
}

// ---------------- fused z aggregation + BCE loss (z0 pre-scaled) ----------------
__global__ void k_zero(float* out) {
    if (blockIdx.x == 0 && threadIdx.x == 0) out[0] = 0.f;
}
__global__ __launch_bounds__(256) void k_zagg_loss(const float* __restrict__ b3,
                                                   const float* __restrict__ y,
                                                   float* __restrict__ out) {
    __shared__ float red[256];
    int i = blockIdx.x * blockDim.x + threadIdx.x;
    float v = 0.f;
    if (i < NN) {
        float dd  = g_dinv[i];
        float acc = g_z0[i];
        int e = g_rowstart[i], end = g_rowstart[i + 1];
        for (; e + 3 < end; e += 4) {
            int s0 = __ldg(&g_csrsrc[e]);
            int s1 = __ldg(&g_csrsrc[e + 1]);
            int s2 = __ldg(&g_csrsrc[e + 2]);
            int s3 = __ldg(&g_csrsrc[e + 3]);
            acc += (__ldg(&g_z0[s0]) + __ldg(&g_z0[s1])) + (__ldg(&g_z0[s2]) + __ldg(&g_z0[s3]));
        }
        for (; e < end; e++) acc += __ldg(&g_z0[__ldg(&g_csrsrc[e])]);
        float z = acc * dd + b3[0];
        float t = y[i];
        v = fmaxf(z, 0.f) - z * t + log1pf(expf(-fabsf(z)));
    }
    red[threadIdx.x] = v;
    __syncthreads();
    for (int s = 128; s > 0; s >>= 1) {
        if (threadIdx.x < s) red[threadIdx.x] += red[threadIdx.x + s];
        __syncthreads();
    }
    if (threadIdx.x == 0) atomicAdd(out, red[0] * (1.0f / NN));
}

// ---------------- launcher ----------------
extern "C" void kernel_launch(void* const* d_in, const int* in_sizes, int n_in,
                              void* d_out, int out_size) {
    const float* x  = (const float*)d_in[0];
    const int*   ei = (const int*)  d_in[1];
    const float* y  = (const float*)d_in[2];
    const float* W1 = (const float*)d_in[3];
    const float* b1 = (const float*)d_in[4];
    const float* W2 = (const float*)d_in[5];
    const float* b2 = (const float*)d_in[6];
    const float* W3 = (const float*)d_in[7];
    const float* b3 = (const float*)d_in[8];
    const int* src = ei;
    const int* dst = ei + NE;
    float* out = (float*)d_out;

    uint32_t *p_xw1, *p_h1;
    float *p_ah1;
    cudaGetSymbolAddress((void**)&p_xw1, g_xw1);
    cudaGetSymbolAddress((void**)&p_h1,  g_h1);
    cudaGetSymbolAddress((void**)&p_ah1, g_ah1);

    cudaFuncSetAttribute(k_gemm1_mma, cudaFuncAttributeMaxDynamicSharedMemorySize, G1_SMEM_BYTES);
    cudaFuncSetAttribute(k_gemm2_mma, cudaFuncAttributeMaxDynamicSharedMemorySize, G1_SMEM_BYTES);

    const int T = 256;
    // ---- CSR build + dinv + weight packs ----
    k_clear<<<(NN + T - 1) / T, T>>>();
    k_packW<<<48, 256>>>(W1, W2);
    k_hist <<<(NE + T - 1) / T, T>>>(dst);
    k_scan1<<<SCAN_NB, SCAN_B>>>();
    k_scan2<<<1, 128>>>();
    k_scan3<<<(NN + T - 1) / T, T>>>();
    k_fill <<<(NE + T - 1) / T, T>>>(src, dst);

    // ---- layer 1 (xw1 bf16, dinv-scaled) ----
    k_gemm1_mma<<<(NN + 255) / 256, 256, G1_SMEM_BYTES>>>(x, p_xw1);
    k_gather_bf2bf<<<(NN * 32 + T - 1) / T, T>>>(p_xw1, p_h1, b1);

    // ---- layer 2 + fused layer-3 matvec ----
    k_gather_bf2f<<<(NN * 32 + T - 1) / T, T>>>(p_h1, p_ah1);
    k_gemm2_mma<<<(NN + 255) / 256, 256, G1_SMEM_BYTES>>>(p_ah1, b2, W3);

    // ---- z aggregation + loss ----
    k_zero<<<1, 32>>>(out);
    k_zagg_loss<<<(NN + T - 1) / T, T>>>(b3, y, out);
}

// round 10
// speedup vs baseline: 2.7904x; 1.0756x over previous
#include <cuda_runtime.h>
#include <cuda_bf16.h>
#include <stdint.h>
#include <math.h>

#define NN 100000
#define NE 1600000
#define FIN 512
#define D1 64
#define D2 256
#define SCAN_B 1024
#define SCAN_NB ((NN + SCAN_B - 1) / SCAN_B)

__device__ float    g_dinv[NN];
__device__ int      g_cnt[NN];
__device__ int      g_tmp[NN];
__device__ int      g_bsum[SCAN_NB];
__device__ int      g_rowstart[NN + 1];
__device__ int      g_csrsrc[NE];
__device__ uint4    g_bfrag[8192];             // packed W1 b-frags
__device__ uint4    g_bfrag2[4096];            // packed W2 b-frags
__device__ uint32_t g_xw1[(size_t)NN * 32];    // bf16x2, dinv-scaled x@W1
__device__ uint32_t g_h1 [(size_t)NN * 32];    // bf16x2, dinv-scaled relu(A xw1 + b1)
__device__ float    g_ah1[(size_t)NN * D1];    // A h1 (fp32)
__device__ float    g_z0 [NN];                 // dinv-scaled h2@W3

// ---------------- bf16 helpers ----------------
__device__ __forceinline__ uint32_t pkbf(float a, float b) {
    __nv_bfloat162 h = __floats2bfloat162_rn(a, b);
    return *(uint32_t*)&h;
}
__device__ __forceinline__ float2 upbf(uint32_t v) {
    __nv_bfloat162 h = *(__nv_bfloat162*)&v;
    return __bfloat1622float2(h);
}
__device__ __forceinline__ float bfres(float f) {
    return f - __bfloat162float(__float2bfloat16(f));
}
__device__ __forceinline__ void mma_bf16(float* c, const uint32_t* a, uint32_t b0, uint32_t b1) {
    asm("mma.sync.aligned.m16n8k16.row.col.f32.bf16.bf16.f32 "
        "{%0,%1,%2,%3}, {%4,%5,%6,%7}, {%8,%9}, {%0,%1,%2,%3};"
        : "+f"(c[0]), "+f"(c[1]), "+f"(c[2]), "+f"(c[3])
        : "r"(a[0]), "r"(a[1]), "r"(a[2]), "r"(a[3]), "r"(b0), "r"(b1));
}

// ---------------- CSR build ----------------
__global__ void k_clear() {
    int i = blockIdx.x * blockDim.x + threadIdx.x;
    if (i < NN) g_cnt[i] = 0;
}
__global__ void k_hist(const int* __restrict__ dst) {
    int e = blockIdx.x * blockDim.x + threadIdx.x;
    if (e < NE) atomicAdd(&g_cnt[dst[e]], 1);
}
__global__ void k_dinv() {
    int i = blockIdx.x * blockDim.x + threadIdx.x;
    if (i < NN) g_dinv[i] = rsqrtf((float)g_cnt[i] + 1.0f);
}
__global__ __launch_bounds__(SCAN_B) void k_scan1() {
    __shared__ int sh[SCAN_B];
    int t = threadIdx.x;
    int i = blockIdx.x * SCAN_B + t;
    sh[t] = (i < NN) ? g_cnt[i] : 0;
    __syncthreads();
#pragma unroll
    for (int off = 1; off < SCAN_B; off <<= 1) {
        int v = (t >= off) ? sh[t - off] : 0;
        __syncthreads();
        sh[t] += v;
        __syncthreads();
    }
    if (i < NN) g_tmp[i] = sh[t];
    if (t == SCAN_B - 1) g_bsum[blockIdx.x] = sh[t];
}
__global__ __launch_bounds__(128) void k_scan2() {
    __shared__ int sh[128];
    int t = threadIdx.x;
    int v0 = (t < SCAN_NB) ? g_bsum[t] : 0;
    sh[t] = v0;
    __syncthreads();
#pragma unroll
    for (int off = 1; off < 128; off <<= 1) {
        int v = (t >= off) ? sh[t - off] : 0;
        __syncthreads();
        sh[t] += v;
        __syncthreads();
    }
    if (t < SCAN_NB) g_bsum[t] = sh[t] - v0;
}
__global__ void k_scan3() {
    int i = blockIdx.x * blockDim.x + threadIdx.x;
    if (i < NN) {
        g_rowstart[i + 1] = g_tmp[i] + g_bsum[i >> 10];
        if (i == 0) g_rowstart[0] = 0;
        g_cnt[i] = 0;
    }
}
__global__ void k_fill(const int* __restrict__ src, const int* __restrict__ dst) {
    int e = blockIdx.x * blockDim.x + threadIdx.x;
    if (e < NE) {
        int d = dst[e];
        int pos = g_rowstart[d] + atomicAdd(&g_cnt[d], 1);
        g_csrsrc[pos] = src[e];
    }
}

// ---------------- pack W1 [512,64] + W2 [64,256] into mma b-fragments ----------------
__global__ void k_packW(const float* __restrict__ B1, const float* __restrict__ B2) {
    int e = blockIdx.x * blockDim.x + threadIdx.x;
    if (e < 8192) {
        int l = e & 31, j = (e >> 5) & 7, s = e >> 8;
        int g = l >> 2, t = l & 3;
        int n = 8 * j + g;
        int k = 16 * s + 2 * t;
        float f0 = B1[(size_t)k * 64 + n];
        float f1 = B1[(size_t)(k + 1) * 64 + n];
        float f2 = B1[(size_t)(k + 8) * 64 + n];
        float f3 = B1[(size_t)(k + 9) * 64 + n];
        g_bfrag[e] = make_uint4(pkbf(f0, f1), pkbf(f2, f3),
                                pkbf(bfres(f0), bfres(f1)), pkbf(bfres(f2), bfres(f3)));
    } else if (e < 8192 + 4096) {
        int e2 = e - 8192;
        int l = e2 & 31, j = (e2 >> 5) & 31, s = e2 >> 10;
        int g = l >> 2, t = l & 3;
        int n = 8 * j + g;
        int k = 16 * s + 2 * t;
        float f0 = B2[(size_t)k * D2 + n];
        float f1 = B2[(size_t)(k + 1) * D2 + n];
        float f2 = B2[(size_t)(k + 8) * D2 + n];
        float f3 = B2[(size_t)(k + 9) * D2 + n];
        g_bfrag2[e2] = make_uint4(pkbf(f0, f1), pkbf(f2, f3),
                                  pkbf(bfres(f0), bfres(f1)), pkbf(bfres(f2), bfres(f3)));
    }
}

// ---------------- GEMM1 via mma.sync bf16 split-3; writes dinv-scaled bf16x2 ----------------
#define G1A_STRIDE 36
#define G1_SMEM_BYTES (2 * 256 * 72 * 2)
__global__ __launch_bounds__(256) void k_gemm1_mma(const float* __restrict__ A,
                                                   uint32_t* __restrict__ C) {
    extern __shared__ char smem[];
    uint32_t* Ah = (uint32_t*)smem;
    uint32_t* Al = (uint32_t*)(smem + 256 * 72 * 2);
    int tid  = threadIdx.x;
    int lane = tid & 31;
    int w    = tid >> 5;
    int g    = lane >> 2;
    int t    = lane & 3;
    int bm   = blockIdx.x * 256;

    float acc[2][8][4];
#pragma unroll
    for (int m = 0; m < 2; m++)
#pragma unroll
        for (int j = 0; j < 8; j++)
#pragma unroll
            for (int q = 0; q < 4; q++) acc[m][j][q] = 0.f;

    int lr = tid >> 4;
    int c4 = (tid & 15) * 4;

    for (int ch = 0; ch < 8; ch++) {
        int k0 = ch * 64;
#pragma unroll
        for (int i = 0; i < 16; i++) {
            int row  = lr + 16 * i;
            int grow = bm + row;
            float4 v = (grow < NN) ? *(const float4*)(A + (size_t)grow * FIN + k0 + c4)
                                   : make_float4(0.f, 0.f, 0.f, 0.f);
            int idx = row * G1A_STRIDE + (c4 >> 1);
            *(uint2*)&Ah[idx] = make_uint2(pkbf(v.x, v.y), pkbf(v.z, v.w));
            *(uint2*)&Al[idx] = make_uint2(pkbf(bfres(v.x), bfres(v.y)), pkbf(bfres(v.z), bfres(v.w)));
        }
        __syncthreads();
#pragma unroll
        for (int s4 = 0; s4 < 4; s4++) {
            int kk = s4 * 16;
            int gs = ch * 4 + s4;
            uint32_t ah[2][4], al[2][4];
#pragma unroll
            for (int m = 0; m < 2; m++) {
                int r0 = w * 32 + m * 16 + g;
                int kc = (kk + 2 * t) >> 1;
                ah[m][0] = Ah[r0 * G1A_STRIDE + kc];
                ah[m][1] = Ah[(r0 + 8) * G1A_STRIDE + kc];
                ah[m][2] = Ah[r0 * G1A_STRIDE + kc + 4];
                ah[m][3] = Ah[(r0 + 8) * G1A_STRIDE + kc + 4];
                al[m][0] = Al[r0 * G1A_STRIDE + kc];
                al[m][1] = Al[(r0 + 8) * G1A_STRIDE + kc];
                al[m][2] = Al[r0 * G1A_STRIDE + kc + 4];
                al[m][3] = Al[(r0 + 8) * G1A_STRIDE + kc + 4];
            }
#pragma unroll
            for (int j = 0; j < 8; j++) {
                uint4 bf4 = __ldg(&g_bfrag[(gs * 8 + j) * 32 + lane]);
#pragma unroll
                for (int m = 0; m < 2; m++) {
                    mma_bf16(acc[m][j], ah[m], bf4.x, bf4.y);
                    mma_bf16(acc[m][j], ah[m], bf4.z, bf4.w);
                    mma_bf16(acc[m][j], al[m], bf4.x, bf4.y);
                }
            }
        }
        __syncthreads();
    }
#pragma unroll
    for (int m = 0; m < 2; m++) {
        int row = bm + w * 32 + m * 16 + g;
        float d0 = (row < NN)     ? g_dinv[row]     : 0.f;
        float d1 = (row + 8 < NN) ? g_dinv[row + 8] : 0.f;
#pragma unroll
        for (int j = 0; j < 8; j++) {
            int cp = 4 * j + t;
            if (row < NN)
                C[(size_t)row * 32 + cp] = pkbf(acc[m][j][0] * d0, acc[m][j][1] * d0);
            if (row + 8 < NN)
                C[(size_t)(row + 8) * 32 + cp] = pkbf(acc[m][j][2] * d1, acc[m][j][3] * d1);
        }
    }
}

// ---------------- gather 1: bf16 in -> bf16 out (relu+bias, dinv^2 scaling), unroll 8 ----
__global__ __launch_bounds__(256) void k_gather_bf2bf(const uint32_t* __restrict__ in,
                                                      uint32_t* __restrict__ out,
                                                      const float* __restrict__ bias) {
    int node = (blockIdx.x * blockDim.x + threadIdx.x) >> 5;
    if (node >= NN) return;
    int lane = threadIdx.x & 31;
    float dd = g_dinv[node];
    float2 self = upbf(in[node * 32 + lane]);
    float ax = self.x, ay = self.y;
    int e   = g_rowstart[node];
    int end = g_rowstart[node + 1];
    for (; e + 7 < end; e += 8) {
        int s[8];
#pragma unroll
        for (int q = 0; q < 8; q++) s[q] = __ldg(&g_csrsrc[e + q]);
        float2 v[8];
#pragma unroll
        for (int q = 0; q < 8; q++) v[q] = upbf(__ldg(&in[s[q] * 32 + lane]));
#pragma unroll
        for (int q = 0; q < 8; q++) { ax += v[q].x; ay += v[q].y; }
    }
    for (; e + 3 < end; e += 4) {
        int s[4];
#pragma unroll
        for (int q = 0; q < 4; q++) s[q] = __ldg(&g_csrsrc[e + q]);
        float2 v[4];
#pragma unroll
        for (int q = 0; q < 4; q++) v[q] = upbf(__ldg(&in[s[q] * 32 + lane]));
#pragma unroll
        for (int q = 0; q < 4; q++) { ax += v[q].x; ay += v[q].y; }
    }
    for (; e < end; e++) {
        float2 v = upbf(__ldg(&in[__ldg(&g_csrsrc[e]) * 32 + lane]));
        ax += v.x;
        ay += v.y;
    }
    float2 bb = ((const float2*)bias)[lane];
    ax = fmaxf(ax * dd + bb.x, 0.f) * dd;
    ay = fmaxf(ay * dd + bb.y, 0.f) * dd;
    out[node * 32 + lane] = pkbf(ax, ay);
}

// ---------------- gather 2: bf16 in -> fp32 out (plain aggregate, dinv scale), unroll 8 ----
__global__ __launch_bounds__(256) void k_gather_bf2f(const uint32_t* __restrict__ in,
                                                     float* __restrict__ out) {
    int node = (blockIdx.x * blockDim.x + threadIdx.x) >> 5;
    if (node >= NN) return;
    int lane = threadIdx.x & 31;
    float dd = g_dinv[node];
    float2 self = upbf(in[node * 32 + lane]);
    float ax = self.x, ay = self.y;
    int e   = g_rowstart[node];
    int end = g_rowstart[node + 1];
    for (; e + 7 < end; e += 8) {
        int s[8];
#pragma unroll
        for (int q = 0; q < 8; q++) s[q] = __ldg(&g_csrsrc[e + q]);
        float2 v[8];
#pragma unroll
        for (int q = 0; q < 8; q++) v[q] = upbf(__ldg(&in[s[q] * 32 + lane]));
#pragma unroll
        for (int q = 0; q < 8; q++) { ax += v[q].x; ay += v[q].y; }
    }
    for (; e + 3 < end; e += 4) {
        int s[4];
#pragma unroll
        for (int q = 0; q < 4; q++) s[q] = __ldg(&g_csrsrc[e + q]);
        float2 v[4];
#pragma unroll
        for (int q = 0; q < 4; q++) v[q] = upbf(__ldg(&in[s[q] * 32 + lane]));
#pragma unroll
        for (int q = 0; q < 4; q++) { ax += v[q].x; ay += v[q].y; }
    }
    for (; e < end; e++) {
        float2 v = upbf(__ldg(&in[__ldg(&g_csrsrc[e]) * 32 + lane]));
        ax += v.x;
        ay += v.y;
    }
    ((float2*)(out + (size_t)node * 64))[lane] = make_float2(ax * dd, ay * dd);
}

// ---------------- GEMM2: one block per 256 rows, loops all 4 n-chunks; writes scaled z0 ----
__global__ __launch_bounds__(256) void k_gemm2_mma(const float* __restrict__ A,
                                                   const float* __restrict__ bias,
                                                   const float* __restrict__ W3) {
    extern __shared__ char smem[];
    uint32_t* Ah = (uint32_t*)smem;
    uint32_t* Al = (uint32_t*)(smem + 256 * 72 * 2);
    __shared__ float zpart[256];
    int tid  = threadIdx.x;
    int lane = tid & 31;
    int w    = tid >> 5;
    int g    = lane >> 2;
    int t    = lane & 3;
    int bm   = blockIdx.x * 256;
    zpart[tid] = 0.f;

    int lr = tid >> 4;
    int c4 = (tid & 15) * 4;
#pragma unroll
    for (int i = 0; i < 16; i++) {
        int row  = lr + 16 * i;
        int grow = bm + row;
        float4 v = (grow < NN) ? *(const float4*)(A + (size_t)grow * D1 + c4)
                               : make_float4(0.f, 0.f, 0.f, 0.f);
        int idx = row * G1A_STRIDE + (c4 >> 1);
        *(uint2*)&Ah[idx] = make_uint2(pkbf(v.x, v.y), pkbf(v.z, v.w));
        *(uint2*)&Al[idx] = make_uint2(pkbf(bfres(v.x), bfres(v.y)), pkbf(bfres(v.z), bfres(v.w)));
    }
    __syncthreads();

    for (int c = 0; c < 4; c++) {
        float acc[2][8][4];
#pragma unroll
        for (int m = 0; m < 2; m++)
#pragma unroll
            for (int j = 0; j < 8; j++)
#pragma unroll
                for (int q = 0; q < 4; q++) acc[m][j][q] = 0.f;
#pragma unroll
        for (int s4 = 0; s4 < 4; s4++) {
            int kk = s4 * 16;
            uint32_t ah[2][4], al[2][4];
#pragma unroll
            for (int m = 0; m < 2; m++) {
                int r0 = w * 32 + m * 16 + g;
                int kc = (kk + 2 * t) >> 1;
                ah[m][0] = Ah[r0 * G1A_STRIDE + kc];
                ah[m][1] = Ah[(r0 + 8) * G1A_STRIDE + kc];
                ah[m][2] = Ah[r0 * G1A_STRIDE + kc + 4];
                ah[m][3] = Ah[(r0 + 8) * G1A_STRIDE + kc + 4];
                al[m][0] = Al[r0 * G1A_STRIDE + kc];
                al[m][1] = Al[(r0 + 8) * G1A_STRIDE + kc];
                al[m][2] = Al[r0 * G1A_STRIDE + kc + 4];
                al[m][3] = Al[(r0 + 8) * G1A_STRIDE + kc + 4];
            }
#pragma unroll
            for (int j = 0; j < 8; j++) {
                uint4 bf4 = __ldg(&g_bfrag2[(s4 * 32 + c * 8 + j) * 32 + lane]);
#pragma unroll
                for (int m = 0; m < 2; m++) {
                    mma_bf16(acc[m][j], ah[m], bf4.x, bf4.y);
                    mma_bf16(acc[m][j], ah[m], bf4.z, bf4.w);
                    mma_bf16(acc[m][j], al[m], bf4.x, bf4.y);
                }
            }
        }
#pragma unroll
        for (int m = 0; m < 2; m++) {
            int rl0 = w * 32 + m * 16 + g;
            float s0 = 0.f, s1 = 0.f;
#pragma unroll
            for (int j = 0; j < 8; j++) {
                int col = c * 64 + 8 * j + 2 * t;
                float b0 = bias[col], b1 = bias[col + 1];
                float w0 = W3[col],  w1 = W3[col + 1];
                s0 += fmaxf(acc[m][j][0] + b0, 0.f) * w0 + fmaxf(acc[m][j][1] + b1, 0.f) * w1;
                s1 += fmaxf(acc[m][j][2] + b0, 0.f) * w0 + fmaxf(acc[m][j][3] + b1, 0.f) * w1;
            }
            atomicAdd(&zpart[rl0],     s0);
            atomicAdd(&zpart[rl0 + 8], s1);
        }
    }
    __syncthreads();
    int row = bm + tid;
    if (row < NN) g_z0[row] = zpart[tid] * g_dinv[row];
}

// ---------------- fused z aggregation + BCE loss (z0 pre-scaled) ----------------
__global__ void k_zero(float* out) {
    if (blockIdx.x == 0 && threadIdx.x == 0) out[0] = 0.f;
}
__global__ __launch_bounds__(256) void k_zagg_loss(const float* __restrict__ b3,
                                                   const float* __restrict__ y,
                                                   float* __restrict__ out) {
    __shared__ float red[256];
    int i = blockIdx.x * blockDim.x + threadIdx.x;
    float v = 0.f;
    if (i < NN) {
        float dd  = g_dinv[i];
        float acc = g_z0[i];
        int e = g_rowstart[i], end = g_rowstart[i + 1];
        for (; e + 7 < end; e += 8) {
            int s[8];
#pragma unroll
            for (int q = 0; q < 8; q++) s[q] = __ldg(&g_csrsrc[e + q]);
            float vv = 0.f;
#pragma unroll
            for (int q = 0; q < 8; q++) vv += __ldg(&g_z0[s[q]]);
            acc += vv;
        }
        for (; e < end; e++) acc += __ldg(&g_z0[__ldg(&g_csrsrc[e])]);
        float z = acc * dd + b3[0];
        float t = y[i];
        v = fmaxf(z, 0.f) - z * t + log1pf(expf(-fabsf(z)));
    }
    red[threadIdx.x] = v;
    __syncthreads();
    for (int s = 128; s > 0; s >>= 1) {
        if (threadIdx.x < s) red[threadIdx.x] += red[threadIdx.x + s];
        __syncthreads();
    }
    if (threadIdx.x == 0) atomicAdd(out, red[0] * (1.0f / NN));
}

// ---------------- launcher ----------------
static cudaStream_t g_s2 = 0;
static cudaEvent_t  g_evFork = 0, g_evJoin = 0;

extern "C" void kernel_launch(void* const* d_in, const int* in_sizes, int n_in,
                              void* d_out, int out_size) {
    const float* x  = (const float*)d_in[0];
    const int*   ei = (const int*)  d_in[1];
    const float* y  = (const float*)d_in[2];
    const float* W1 = (const float*)d_in[3];
    const float* b1 = (const float*)d_in[4];
    const float* W2 = (const float*)d_in[5];
    const float* b2 = (const float*)d_in[6];
    const float* W3 = (const float*)d_in[7];
    const float* b3 = (const float*)d_in[8];
    const int* src = ei;
    const int* dst = ei + NE;
    float* out = (float*)d_out;

    uint32_t *p_xw1, *p_h1;
    float *p_ah1;
    cudaGetSymbolAddress((void**)&p_xw1, g_xw1);
    cudaGetSymbolAddress((void**)&p_h1,  g_h1);
    cudaGetSymbolAddress((void**)&p_ah1, g_ah1);

    cudaFuncSetAttribute(k_gemm1_mma, cudaFuncAttributeMaxDynamicSharedMemorySize, G1_SMEM_BYTES);
    cudaFuncSetAttribute(k_gemm2_mma, cudaFuncAttributeMaxDynamicSharedMemorySize, G1_SMEM_BYTES);

    if (!g_s2) {
        cudaStreamCreateWithFlags(&g_s2, cudaStreamNonBlocking);
        cudaEventCreateWithFlags(&g_evFork, cudaEventDisableTiming);
        cudaEventCreateWithFlags(&g_evJoin, cudaEventDisableTiming);
    }

    const int T = 256;
    // ---- prefix on default stream: degree histogram + dinv ----
    k_clear<<<(NN + T - 1) / T, T>>>();
    k_hist <<<(NE + T - 1) / T, T>>>(dst);
    k_dinv <<<(NN + T - 1) / T, T>>>();

    // ---- fork: CSR (scan+fill) on s2  ||  packW + gemm1 on default ----
    cudaEventRecord(g_evFork, 0);
    cudaStreamWaitEvent(g_s2, g_evFork, 0);
    k_scan1<<<SCAN_NB, SCAN_B, 0, g_s2>>>();
    k_scan2<<<1, 128, 0, g_s2>>>();
    k_scan3<<<(NN + T - 1) / T, T, 0, g_s2>>>();
    k_fill <<<(NE + T - 1) / T, T, 0, g_s2>>>(src, dst);
    cudaEventRecord(g_evJoin, g_s2);

    k_packW<<<48, 256>>>(W1, W2);
    k_gemm1_mma<<<(NN + 255) / 256, 256, G1_SMEM_BYTES>>>(x, p_xw1);

    // ---- join ----
    cudaStreamWaitEvent(0, g_evJoin, 0);

    // ---- layer 1 aggregate ----
    k_gather_bf2bf<<<(NN * 32 + T - 1) / T, T>>>(p_xw1, p_h1, b1);

    // ---- layer 2 + fused layer-3 matvec ----
    k_gather_bf2f<<<(NN * 32 + T - 1) / T, T>>>(p_h1, p_ah1);
    k_gemm2_mma<<<(NN + 255) / 256, 256, G1_SMEM_BYTES>>>(p_ah1, b2, W3);

    // ---- z aggregation + loss ----
    k_zero<<<1, 32>>>(out);
    k_zagg_loss<<<(NN + T - 1) / T, T>>>(b3, y, out);
}